// round 3
// baseline (speedup 1.0000x reference)
#include <cuda_runtime.h>
#include <math.h>

// Problem dims (fixed by the reference): B=64, T=512, V=512, E=128, D=256
constexpr int Tn = 512, Bn = 64, Vn = 512, En = 128, Dn = 256;
constexpr int TT = 16;   // query-tile for attention

// Scratch (device globals: allocation-free rule)
__device__ float g_xp [Tn*Bn*Dn];   // input projection  [t][b][d]
__device__ float g_H  [Tn*Bn*Dn];   // hidden states     [t][b][d]
__device__ float g_P  [Tn*Bn*Dn];   // H @ W_attn        [t][b][d]
__device__ float g_C  [Tn*Bn*Dn];   // H @ U_attn        [t][b][d]
__device__ float g_CTX[Tn*Bn*Dn];   // attention context [t][b][d]
__device__ float g_Wt [Dn*Dn];      // W_hh transposed: g_Wt[d*Dn+k] = W_hh[k][d]

// ---------------------------------------------------------------------------
// 0) transpose W_hh (one-time tiny cost per call)
__global__ void k_transpose(const float* __restrict__ W) {
    int k = blockIdx.x, d = threadIdx.x;
    g_Wt[d*Dn + k] = W[k*Dn + d];
}

// ---------------------------------------------------------------------------
// 1) xp[t][b][d] = embed[x[b][t]] @ W_ih + b_h
//    block = 64 rows (r = t*B + b), 256 threads = 256 cols
__global__ void __launch_bounds__(256) k_embed(
    const int* __restrict__ x, const float* __restrict__ embed,
    const float* __restrict__ Wih, const float* __restrict__ bh)
{
    __shared__ float As[En][68];           // A-tile transposed, padded (34.8 KB)
    int r0 = blockIdx.x * 64;
    int tid = threadIdx.x;
    for (int idx = tid; idx < 64*En; idx += 256) {
        int i = idx / En, e = idx % En;
        int r = r0 + i, t = r / Bn, b = r % Bn;
        int tok = x[b*Tn + t];
        As[e][i] = embed[tok*En + e];
    }
    __syncthreads();
    int d = tid;
    float bias = bh[d];
    float acc[64];
#pragma unroll
    for (int i = 0; i < 64; i++) acc[i] = bias;
    for (int e = 0; e < En; e++) {
        float w = Wih[e*Dn + d];
#pragma unroll
        for (int i = 0; i < 64; i += 4) {
            float4 a = *(const float4*)&As[e][i];
            acc[i]   = fmaf(a.x, w, acc[i]);
            acc[i+1] = fmaf(a.y, w, acc[i+1]);
            acc[i+2] = fmaf(a.z, w, acc[i+2]);
            acc[i+3] = fmaf(a.w, w, acc[i+3]);
        }
    }
#pragma unroll
    for (int i = 0; i < 64; i++) g_xp[(r0+i)*Dn + d] = acc[i];
}

// ---------------------------------------------------------------------------
// 2) Recurrence: h_t = tanh(xp_t + h_{t-1} @ W_hh), one CTA per batch row.
//    W column split: k in [0,128) in registers, k in [128,256) in SMEM
//    (lane-contiguous float4 -> conflict-free LDS). No inter-CTA sync needed.
__global__ void __launch_bounds__(256, 1) k_rnn() {
    extern __shared__ float sm[];
    float*  hs = sm;                         // 256 floats
    float4* Ws = (float4*)(sm + 256);        // [32][256] float4 = 128 KB
    int b = blockIdx.x, d = threadIdx.x;

    const float* wtrow = &g_Wt[d*Dn];
    float4 wreg[32];
#pragma unroll
    for (int i = 0; i < 32; i++) wreg[i] = *(const float4*)(wtrow + 4*i);
#pragma unroll
    for (int i = 0; i < 32; i++) Ws[i*256 + d] = *(const float4*)(wtrow + 128 + 4*i);
    hs[d] = 0.f;
    __syncthreads();

    for (int t = 0; t < Tn; t++) {
        float acc  = g_xp[(t*Bn + b)*Dn + d];
        float acc2 = 0.f;
#pragma unroll
        for (int i = 0; i < 32; i++) {
            float4 h = *(const float4*)&hs[4*i];
            acc = fmaf(wreg[i].x, h.x, acc); acc = fmaf(wreg[i].y, h.y, acc);
            acc = fmaf(wreg[i].z, h.z, acc); acc = fmaf(wreg[i].w, h.w, acc);
        }
#pragma unroll
        for (int i = 0; i < 32; i++) {
            float4 w = Ws[i*256 + d];
            float4 h = *(const float4*)&hs[128 + 4*i];
            acc2 = fmaf(w.x, h.x, acc2); acc2 = fmaf(w.y, h.y, acc2);
            acc2 = fmaf(w.z, h.z, acc2); acc2 = fmaf(w.w, h.w, acc2);
        }
        float hv = tanhf(acc + acc2);        // accurate tanh: errors compound here
        __syncthreads();
        hs[d] = hv;
        g_H[(t*Bn + b)*Dn + d] = hv;
        __syncthreads();
    }
}

// ---------------------------------------------------------------------------
// 3) P = H @ W_attn (y=0), C = H @ U_attn (y=1). Same tiling as k_embed, K=256.
__global__ void __launch_bounds__(256) k_proj(
    const float* __restrict__ Wa, const float* __restrict__ Ua)
{
    extern __shared__ float As[];            // [256][68] floats = 69632 B
    int r0 = blockIdx.x * 64;
    int tid = threadIdx.x;
    const float* Wsel = blockIdx.y ? Ua : Wa;
    float*       Out  = blockIdx.y ? g_C : g_P;

    for (int idx = tid; idx < 64*Dn; idx += 256) {
        int i = idx / Dn, k = idx % Dn;
        As[k*68 + i] = g_H[(r0+i)*Dn + k];
    }
    __syncthreads();
    int d = tid;
    float acc[64];
#pragma unroll
    for (int i = 0; i < 64; i++) acc[i] = 0.f;
    for (int k = 0; k < Dn; k++) {
        float w = Wsel[k*Dn + d];
#pragma unroll
        for (int i = 0; i < 64; i += 4) {
            float4 a = *(const float4*)&As[k*68 + i];
            acc[i]   = fmaf(a.x, w, acc[i]);
            acc[i+1] = fmaf(a.y, w, acc[i+1]);
            acc[i+2] = fmaf(a.z, w, acc[i+2]);
            acc[i+3] = fmaf(a.w, w, acc[i+3]);
        }
    }
#pragma unroll
    for (int i = 0; i < 64; i++) Out[(r0+i)*Dn + d] = acc[i];
}

// ---------------------------------------------------------------------------
// 4) Bahdanau attention, tiled: block = (b, 16 queries).
//    energy[tq][tp] = sum_d v[d]*tanh(P[tp]+C[tq]); softmax over tp<tq; ctx.
__global__ void __launch_bounds__(256) k_attn(const float* __restrict__ vat) {
    __shared__ float Cs[TT][Dn - 4];         // 16128 B (only 252 used safely? no)
    // NOTE: Cs must hold full D=256; use separate layout below instead.
    __shared__ float Cs2[TT][4];             // remainder columns 252..255
    __shared__ float EsT[Tn][TT];            // 32 KB  (transposed: [tp][tq])
    int b  = blockIdx.y;
    int t0 = blockIdx.x * TT;
    int tid = threadIdx.x;
    int warp = tid >> 5, lane = tid & 31;

    for (int idx = tid; idx < TT*Dn; idx += 256) {
        int q = idx / Dn, d2 = idx % Dn;
        float v = g_C[((t0+q)*Bn + b)*Dn + d2];
        if (d2 < Dn - 4) Cs[q][d2] = v; else Cs2[q][d2 - (Dn-4)] = v;
    }
    float vreg[8];
#pragma unroll
    for (int j = 0; j < 8; j++) vreg[j] = vat[lane + 32*j];
    __syncthreads();

    int t_hi = t0 + TT;
    // Pass 1: energies (MUFU-bound). Warp handles one key tp at a time.
    for (int tp = warp; tp < t_hi; tp += 8) {
        float p[8];
#pragma unroll
        for (int j = 0; j < 8; j++) p[j] = g_P[(tp*Bn + b)*Dn + lane + 32*j];
#pragma unroll
        for (int q = 0; q < TT; q++) {
            float s = 0.f;
#pragma unroll
            for (int j = 0; j < 8; j++) {
                int d2 = lane + 32*j;
                float cv = (d2 < Dn - 4) ? Cs[q][d2] : Cs2[q][d2 - (Dn-4)];
                float z = p[j] + cv;
                float th; asm("tanh.approx.f32 %0, %1;" : "=f"(th) : "f"(z));
                s = fmaf(vreg[j], th, s);
            }
#pragma unroll
            for (int o = 16; o; o >>= 1) s += __shfl_xor_sync(0xffffffffu, s, o);
            if (lane == 0) EsT[tp][q] = s;
        }
    }
    __syncthreads();

    // Pass 2: masked softmax per query (weights stored back, zeros for tp>=tq)
    for (int q = warp; q < TT; q += 8) {
        int tg = t0 + q;
        float mx = -3.4e38f;
        for (int tp = lane; tp < tg; tp += 32) mx = fmaxf(mx, EsT[tp][q]);
#pragma unroll
        for (int o = 16; o; o >>= 1) mx = fmaxf(mx, __shfl_xor_sync(0xffffffffu, mx, o));
        float sum = 0.f;
        for (int tp = lane; tp < tg; tp += 32) {
            float e = __expf(EsT[tp][q] - mx);
            EsT[tp][q] = e; sum += e;
        }
#pragma unroll
        for (int o = 16; o; o >>= 1) sum += __shfl_xor_sync(0xffffffffu, sum, o);
        float inv = tg > 0 ? 1.f / sum : 0.f;
        for (int tp = lane; tp < t_hi; tp += 32) {
            float wv = (tp < tg) ? EsT[tp][q] * inv : 0.f;
            EsT[tp][q] = wv;
        }
    }
    __syncthreads();

    // Pass 3: ctx[q][d] = sum_tp w * H[tp][b][d]  (float4 weight broadcast)
    int d = tid;
    float acc[TT];
#pragma unroll
    for (int q = 0; q < TT; q++) acc[q] = 0.f;
    int tmax = t0 + TT - 1;                  // max key index needed
    for (int tp = 0; tp < tmax; tp++) {
        float hval = g_H[(tp*Bn + b)*Dn + d];
#pragma unroll
        for (int q = 0; q < TT; q += 4) {
            float4 w = *(const float4*)&EsT[tp][q];
            acc[q]   = fmaf(w.x, hval, acc[q]);
            acc[q+1] = fmaf(w.y, hval, acc[q+1]);
            acc[q+2] = fmaf(w.z, hval, acc[q+2]);
            acc[q+3] = fmaf(w.w, hval, acc[q+3]);
        }
    }
#pragma unroll
    for (int q = 0; q < TT; q++) {
        int tg = t0 + q;
        float c = acc[q];
        if (tg == 0) c = g_H[b*Dn + d];      // t==0: ctx = h itself
        g_CTX[(tg*Bn + b)*Dn + d] = c;
    }
}

// ---------------------------------------------------------------------------
// 5) logits = [H | CTX] @ fc_W + fc_b ; out[b][t][v]
__global__ void __launch_bounds__(512, 1) k_logits(
    const float* __restrict__ fcW, const float* __restrict__ fcb,
    float* __restrict__ out)
{
    __shared__ float As[128*68];             // K-tile transposed (34.8 KB)
    int r0 = blockIdx.x * 64;
    int v = threadIdx.x;
    float bias = fcb[v];
    float acc[64];
#pragma unroll
    for (int i = 0; i < 64; i++) acc[i] = bias;

    for (int k0 = 0; k0 < 2*Dn; k0 += 128) {
        __syncthreads();
        for (int idx = v; idx < 128*64; idx += 512) {
            int i = idx / 128, kk = idx % 128;
            int k = k0 + kk;
            const float* src = (k < Dn) ? g_H : g_CTX;
            int kd = (k < Dn) ? k : k - Dn;
            As[kk*68 + i] = src[(r0+i)*Dn + kd];
        }
        __syncthreads();
        for (int kk = 0; kk < 128; kk++) {
            float w = fcW[(k0+kk)*Vn + v];
#pragma unroll
            for (int i = 0; i < 64; i += 4) {
                float4 a = *(const float4*)&As[kk*68 + i];
                acc[i]   = fmaf(a.x, w, acc[i]);
                acc[i+1] = fmaf(a.y, w, acc[i+1]);
                acc[i+2] = fmaf(a.z, w, acc[i+2]);
                acc[i+3] = fmaf(a.w, w, acc[i+3]);
            }
        }
    }
#pragma unroll
    for (int i = 0; i < 64; i++) {
        int r = r0 + i, t = r / Bn, b = r % Bn;
        out[(b*Tn + t)*Vn + v] = acc[i];
    }
}

// ---------------------------------------------------------------------------
extern "C" void kernel_launch(void* const* d_in, const int* in_sizes, int n_in,
                              void* d_out, int out_size)
{
    const int*   x     = (const int*)  d_in[0];
    const float* embed = (const float*)d_in[1];
    const float* Wih   = (const float*)d_in[2];
    const float* Whh   = (const float*)d_in[3];
    const float* bh    = (const float*)d_in[4];
    const float* Wat   = (const float*)d_in[5];
    const float* Uat   = (const float*)d_in[6];
    const float* vat   = (const float*)d_in[7];
    const float* fcW   = (const float*)d_in[8];
    const float* fcb   = (const float*)d_in[9];
    float* out = (float*)d_out;

    cudaFuncSetAttribute(k_rnn,  cudaFuncAttributeMaxDynamicSharedMemorySize, 256*4 + 32*256*16);
    cudaFuncSetAttribute(k_proj, cudaFuncAttributeMaxDynamicSharedMemorySize, 256*68*4);

    k_transpose<<<Dn, Dn>>>(Whh);
    k_embed<<<(Tn*Bn)/64, 256>>>(x, embed, Wih, bh);
    k_rnn<<<Bn, 256, 256*4 + 32*256*16>>>();
    k_proj<<<dim3((Tn*Bn)/64, 2), 256, 256*68*4>>>(Wat, Uat);
    k_attn<<<dim3(Tn/TT, Bn), 256>>>(vat);
    k_logits<<<(Tn*Bn)/64, 512>>>(fcW, fcb, out);
}

// round 5
// speedup vs baseline: 1.1187x; 1.1187x over previous
#include <cuda_runtime.h>
#include <math.h>

// Problem dims (fixed by the reference): B=64, T=512, V=512, E=128, D=256
constexpr int Tn = 512, Bn = 64, Vn = 512, En = 128, Dn = 256;
constexpr int TT = 16;   // query-tile for attention

// Scratch (device globals: allocation-free rule)
__device__ float g_xp [Tn*Bn*Dn];   // input projection  [t][b][d]
__device__ float g_H  [Tn*Bn*Dn];   // hidden states     [t][b][d]
__device__ float g_P  [Tn*Bn*Dn];   // H @ W_attn        [t][b][d]
__device__ float g_C  [Tn*Bn*Dn];   // H @ U_attn        [t][b][d]
__device__ float g_CTX[Tn*Bn*Dn];   // attention context [t][b][d]
__device__ float g_Wt [Dn*Dn];      // W_hh transposed: g_Wt[d*Dn+k] = W_hh[k][d]

// ---------------------------------------------------------------------------
// 0) transpose W_hh (one-time tiny cost per call)
__global__ void k_transpose(const float* __restrict__ W) {
    int k = blockIdx.x, d = threadIdx.x;
    g_Wt[d*Dn + k] = W[k*Dn + d];
}

// ---------------------------------------------------------------------------
// 1) xp[t][b][d] = embed[x[b][t]] @ W_ih + b_h
//    block = 32 rows (r = t*B + b), 256 threads = 256 cols, acc[32]
__global__ void __launch_bounds__(256, 4) k_embed(
    const int* __restrict__ x, const float* __restrict__ embed,
    const float* __restrict__ Wih, const float* __restrict__ bh)
{
    __shared__ float As[En*36];            // A-tile transposed, padded (18.4 KB)
    __shared__ int   toks[32];
    int r0 = blockIdx.x * 32;
    int tid = threadIdx.x;
    if (tid < 32) {
        int r = r0 + tid, t = r >> 6, b = r & 63;
        toks[tid] = x[b*Tn + t];
    }
    __syncthreads();
    for (int idx = tid; idx < 32*En; idx += 256) {
        int i = idx >> 7, e = idx & 127;
        As[e*36 + i] = embed[toks[i]*En + e];
    }
    __syncthreads();
    int d = tid;
    float bias = bh[d];
    float acc[32];
#pragma unroll
    for (int i = 0; i < 32; i++) acc[i] = bias;
#pragma unroll 4
    for (int e = 0; e < En; e++) {
        float w = Wih[e*Dn + d];
#pragma unroll
        for (int i = 0; i < 32; i += 4) {
            float4 a = *(const float4*)&As[e*36 + i];
            acc[i]   = fmaf(a.x, w, acc[i]);
            acc[i+1] = fmaf(a.y, w, acc[i+1]);
            acc[i+2] = fmaf(a.z, w, acc[i+2]);
            acc[i+3] = fmaf(a.w, w, acc[i+3]);
        }
    }
#pragma unroll
    for (int i = 0; i < 32; i++) g_xp[(r0+i)*Dn + d] = acc[i];
}

// ---------------------------------------------------------------------------
// 2) Recurrence: h_t = tanh(xp_t + h_{t-1} @ W_hh), one CTA per batch row.
//    W column split: k in [0,128) in registers, k in [128,256) in SMEM
//    (lane-contiguous float4 -> conflict-free LDS). No inter-CTA sync needed.
__global__ void __launch_bounds__(256, 1) k_rnn() {
    extern __shared__ float sm[];
    float*  hs = sm;                         // 256 floats
    float4* Ws = (float4*)(sm + 256);        // [32][256] float4 = 128 KB
    int b = blockIdx.x, d = threadIdx.x;

    const float* wtrow = &g_Wt[d*Dn];
    float4 wreg[32];
#pragma unroll
    for (int i = 0; i < 32; i++) wreg[i] = *(const float4*)(wtrow + 4*i);
#pragma unroll
    for (int i = 0; i < 32; i++) Ws[i*256 + d] = *(const float4*)(wtrow + 128 + 4*i);
    hs[d] = 0.f;
    __syncthreads();

    for (int t = 0; t < Tn; t++) {
        float acc  = g_xp[(t*Bn + b)*Dn + d];
        float acc2 = 0.f;
#pragma unroll
        for (int i = 0; i < 32; i++) {
            float4 h = *(const float4*)&hs[4*i];
            acc = fmaf(wreg[i].x, h.x, acc); acc = fmaf(wreg[i].y, h.y, acc);
            acc = fmaf(wreg[i].z, h.z, acc); acc = fmaf(wreg[i].w, h.w, acc);
        }
#pragma unroll
        for (int i = 0; i < 32; i++) {
            float4 w = Ws[i*256 + d];
            float4 h = *(const float4*)&hs[128 + 4*i];
            acc2 = fmaf(w.x, h.x, acc2); acc2 = fmaf(w.y, h.y, acc2);
            acc2 = fmaf(w.z, h.z, acc2); acc2 = fmaf(w.w, h.w, acc2);
        }
        float hv = tanhf(acc + acc2);        // accurate tanh: errors compound here
        __syncthreads();
        hs[d] = hv;
        g_H[(t*Bn + b)*Dn + d] = hv;
        __syncthreads();
    }
}

// ---------------------------------------------------------------------------
// 3) P = H @ W_attn (y=0), C = H @ U_attn (y=1). 32-row tiles, acc[32], K=256.
__global__ void __launch_bounds__(256, 4) k_proj(
    const float* __restrict__ Wa, const float* __restrict__ Ua)
{
    __shared__ float As[Dn*36];              // [256][36] floats = 36864 B
    int r0 = blockIdx.x * 32;
    int tid = threadIdx.x;
    const float* Wsel = blockIdx.y ? Ua : Wa;
    float*       Out  = blockIdx.y ? g_C : g_P;

    for (int idx = tid; idx < 32*Dn; idx += 256) {
        int i = idx >> 8, k = idx & 255;
        As[k*36 + i] = g_H[(r0+i)*Dn + k];
    }
    __syncthreads();
    int d = tid;
    float acc[32];
#pragma unroll
    for (int i = 0; i < 32; i++) acc[i] = 0.f;
#pragma unroll 4
    for (int k = 0; k < Dn; k++) {
        float w = Wsel[k*Dn + d];
#pragma unroll
        for (int i = 0; i < 32; i += 4) {
            float4 a = *(const float4*)&As[k*36 + i];
            acc[i]   = fmaf(a.x, w, acc[i]);
            acc[i+1] = fmaf(a.y, w, acc[i+1]);
            acc[i+2] = fmaf(a.z, w, acc[i+2]);
            acc[i+3] = fmaf(a.w, w, acc[i+3]);
        }
    }
#pragma unroll
    for (int i = 0; i < 32; i++) Out[(r0+i)*Dn + d] = acc[i];
}

// ---------------------------------------------------------------------------
// 4) Bahdanau attention, tiled: block = (b, 16 queries).  (unchanged — passed)
//    energy[tq][tp] = sum_d v[d]*tanh(P[tp]+C[tq]); softmax over tp<tq; ctx.
__global__ void __launch_bounds__(256) k_attn(const float* __restrict__ vat) {
    __shared__ float Cs[TT][Dn - 4];         // columns 0..251
    __shared__ float Cs2[TT][4];             // remainder columns 252..255
    __shared__ float EsT[Tn][TT];            // 32 KB  (transposed: [tp][tq])
    int b  = blockIdx.y;
    int t0 = blockIdx.x * TT;
    int tid = threadIdx.x;
    int warp = tid >> 5, lane = tid & 31;

    for (int idx = tid; idx < TT*Dn; idx += 256) {
        int q = idx / Dn, d2 = idx % Dn;
        float v = g_C[((t0+q)*Bn + b)*Dn + d2];
        if (d2 < Dn - 4) Cs[q][d2] = v; else Cs2[q][d2 - (Dn-4)] = v;
    }
    float vreg[8];
#pragma unroll
    for (int j = 0; j < 8; j++) vreg[j] = vat[lane + 32*j];
    __syncthreads();

    int t_hi = t0 + TT;
    // Pass 1: energies (MUFU-bound). Warp handles one key tp at a time.
    for (int tp = warp; tp < t_hi; tp += 8) {
        float p[8];
#pragma unroll
        for (int j = 0; j < 8; j++) p[j] = g_P[(tp*Bn + b)*Dn + lane + 32*j];
#pragma unroll
        for (int q = 0; q < TT; q++) {
            float s = 0.f;
#pragma unroll
            for (int j = 0; j < 8; j++) {
                int d2 = lane + 32*j;
                float cv = (d2 < Dn - 4) ? Cs[q][d2] : Cs2[q][d2 - (Dn-4)];
                float z = p[j] + cv;
                float th; asm("tanh.approx.f32 %0, %1;" : "=f"(th) : "f"(z));
                s = fmaf(vreg[j], th, s);
            }
#pragma unroll
            for (int o = 16; o; o >>= 1) s += __shfl_xor_sync(0xffffffffu, s, o);
            if (lane == 0) EsT[tp][q] = s;
        }
    }
    __syncthreads();

    // Pass 2: masked softmax per query (weights stored back, zeros for tp>=tq)
    for (int q = warp; q < TT; q += 8) {
        int tg = t0 + q;
        float mx = -3.4e38f;
        for (int tp = lane; tp < tg; tp += 32) mx = fmaxf(mx, EsT[tp][q]);
#pragma unroll
        for (int o = 16; o; o >>= 1) mx = fmaxf(mx, __shfl_xor_sync(0xffffffffu, mx, o));
        float sum = 0.f;
        for (int tp = lane; tp < tg; tp += 32) {
            float e = __expf(EsT[tp][q] - mx);
            EsT[tp][q] = e; sum += e;
        }
#pragma unroll
        for (int o = 16; o; o >>= 1) sum += __shfl_xor_sync(0xffffffffu, sum, o);
        float inv = tg > 0 ? 1.f / sum : 0.f;
        for (int tp = lane; tp < t_hi; tp += 32) {
            float wv = (tp < tg) ? EsT[tp][q] * inv : 0.f;
            EsT[tp][q] = wv;
        }
    }
    __syncthreads();

    // Pass 3: ctx[q][d] = sum_tp w * H[tp][b][d]  (float4 weight broadcast)
    int d = tid;
    float acc[TT];
#pragma unroll
    for (int q = 0; q < TT; q++) acc[q] = 0.f;
    int tmax = t0 + TT - 1;                  // max key index needed
    for (int tp = 0; tp < tmax; tp++) {
        float hval = g_H[(tp*Bn + b)*Dn + d];
#pragma unroll
        for (int q = 0; q < TT; q += 4) {
            float4 w = *(const float4*)&EsT[tp][q];
            acc[q]   = fmaf(w.x, hval, acc[q]);
            acc[q+1] = fmaf(w.y, hval, acc[q+1]);
            acc[q+2] = fmaf(w.z, hval, acc[q+2]);
            acc[q+3] = fmaf(w.w, hval, acc[q+3]);
        }
    }
#pragma unroll
    for (int q = 0; q < TT; q++) {
        int tg = t0 + q;
        float c = acc[q];
        if (tg == 0) c = g_H[b*Dn + d];      // t==0: ctx = h itself
        g_CTX[(tg*Bn + b)*Dn + d] = c;
    }
}

// ---------------------------------------------------------------------------
// 5) logits = [H | CTX] @ fc_W + fc_b ; out[b][t][v]
//    32-row tiles, 512 threads = 512 V-cols, acc[32], 4 K-tiles of 128.
__global__ void __launch_bounds__(512, 2) k_logits(
    const float* __restrict__ fcW, const float* __restrict__ fcb,
    float* __restrict__ out)
{
    __shared__ float As[128*36];             // K-tile transposed (18.4 KB)
    int r0 = blockIdx.x * 32;
    int v = threadIdx.x;
    float bias = fcb[v];
    float acc[32];
#pragma unroll
    for (int i = 0; i < 32; i++) acc[i] = bias;

    for (int k0 = 0; k0 < 2*Dn; k0 += 128) {
        __syncthreads();
        for (int idx = v; idx < 32*128; idx += 512) {
            int i = idx >> 7, kk = idx & 127;
            int k = k0 + kk;
            const float* src = (k < Dn) ? g_H : g_CTX;
            int kd = k & (Dn - 1);
            As[kk*36 + i] = src[(r0+i)*Dn + kd];
        }
        __syncthreads();
#pragma unroll 4
        for (int kk = 0; kk < 128; kk++) {
            float w = fcW[(k0+kk)*Vn + v];
#pragma unroll
            for (int i = 0; i < 32; i += 4) {
                float4 a = *(const float4*)&As[kk*36 + i];
                acc[i]   = fmaf(a.x, w, acc[i]);
                acc[i+1] = fmaf(a.y, w, acc[i+1]);
                acc[i+2] = fmaf(a.z, w, acc[i+2]);
                acc[i+3] = fmaf(a.w, w, acc[i+3]);
            }
        }
    }
#pragma unroll
    for (int i = 0; i < 32; i++) {
        int r = r0 + i, t = r >> 6, b = r & 63;
        out[(b*Tn + t)*Vn + v] = acc[i];
    }
}

// ---------------------------------------------------------------------------
extern "C" void kernel_launch(void* const* d_in, const int* in_sizes, int n_in,
                              void* d_out, int out_size)
{
    const int*   x     = (const int*)  d_in[0];
    const float* embed = (const float*)d_in[1];
    const float* Wih   = (const float*)d_in[2];
    const float* Whh   = (const float*)d_in[3];
    const float* bh    = (const float*)d_in[4];
    const float* Wat   = (const float*)d_in[5];
    const float* Uat   = (const float*)d_in[6];
    const float* vat   = (const float*)d_in[7];
    const float* fcW   = (const float*)d_in[8];
    const float* fcb   = (const float*)d_in[9];
    float* out = (float*)d_out;

    cudaFuncSetAttribute(k_rnn, cudaFuncAttributeMaxDynamicSharedMemorySize, 256*4 + 32*256*16);

    k_transpose<<<Dn, Dn>>>(Whh);
    k_embed<<<(Tn*Bn)/32, 256>>>(x, embed, Wih, bh);
    k_rnn<<<Bn, 256, 256*4 + 32*256*16>>>();
    k_proj<<<dim3((Tn*Bn)/32, 2), 256>>>(Wat, Uat);
    k_attn<<<dim3(Tn/TT, Bn), 256>>>(vat);
    k_logits<<<(Tn*Bn)/32, 512>>>(fcW, fcb, out);
}

// round 6
// speedup vs baseline: 1.1549x; 1.0323x over previous
#include <cuda_runtime.h>
#include <math.h>

// Problem dims (fixed by the reference): B=64, T=512, V=512, E=128, D=256
constexpr int Tn = 512, Bn = 64, Vn = 512, En = 128, Dn = 256;
constexpr int TT = 16;   // query-tile for attention

// Scratch (device globals: allocation-free rule)
__device__ float g_xp [Tn*Bn*Dn];   // input projection  [t][b][d]
__device__ float g_H  [Tn*Bn*Dn];   // hidden states     [t][b][d]
__device__ float g_P  [Tn*Bn*Dn];   // H @ W_attn        [t][b][d]
__device__ float g_C  [Tn*Bn*Dn];   // H @ U_attn        [t][b][d]
__device__ float g_CTX[Tn*Bn*Dn];   // attention context [t][b][d]
__device__ float g_Wt [Dn*Dn];      // W_hh transposed: g_Wt[d*Dn+k] = W_hh[k][d]

// ---------------------------------------------------------------------------
// 0) transpose W_hh (one-time tiny cost per call)
__global__ void k_transpose(const float* __restrict__ W) {
    int k = blockIdx.x, d = threadIdx.x;
    g_Wt[d*Dn + k] = W[k*Dn + d];
}

// ===========================================================================
// Shared 64x64 GEMM tile core: 256 thr = 16x16, each 4x4.
//   As[kk*68 + i]  : A^T tile (68-pad: float4-aligned, 4-way write conflict ok)
//   Ws[kk*68 + dd] : W tile
// Per k: 2 LDS.128 + 16 FMA  (FMA:LDS = 8:1)
// ===========================================================================
#define GEMM_CORE(KT)                                                        \
    {                                                                        \
        _Pragma("unroll 8")                                                  \
        for (int kk = 0; kk < (KT); kk++) {                                  \
            float4 a = *(const float4*)&As[kk*68 + ty4];                     \
            float4 w = *(const float4*)&Ws[kk*68 + tx4];                     \
            acc[0][0] = fmaf(a.x, w.x, acc[0][0]);                           \
            acc[0][1] = fmaf(a.x, w.y, acc[0][1]);                           \
            acc[0][2] = fmaf(a.x, w.z, acc[0][2]);                           \
            acc[0][3] = fmaf(a.x, w.w, acc[0][3]);                           \
            acc[1][0] = fmaf(a.y, w.x, acc[1][0]);                           \
            acc[1][1] = fmaf(a.y, w.y, acc[1][1]);                           \
            acc[1][2] = fmaf(a.y, w.z, acc[1][2]);                           \
            acc[1][3] = fmaf(a.y, w.w, acc[1][3]);                           \
            acc[2][0] = fmaf(a.z, w.x, acc[2][0]);                           \
            acc[2][1] = fmaf(a.z, w.y, acc[2][1]);                           \
            acc[2][2] = fmaf(a.z, w.z, acc[2][2]);                           \
            acc[2][3] = fmaf(a.z, w.w, acc[2][3]);                           \
            acc[3][0] = fmaf(a.w, w.x, acc[3][0]);                           \
            acc[3][1] = fmaf(a.w, w.y, acc[3][1]);                           \
            acc[3][2] = fmaf(a.w, w.z, acc[3][2]);                           \
            acc[3][3] = fmaf(a.w, w.w, acc[3][3]);                           \
        }                                                                    \
    }

// ---------------------------------------------------------------------------
// 1) xp = embed[x] @ W_ih + b_h.   M=32768, N=256, K=128. grid(512,4)
__global__ void __launch_bounds__(256, 4) k_embed(
    const int* __restrict__ x, const float* __restrict__ embed,
    const float* __restrict__ Wih, const float* __restrict__ bh)
{
    __shared__ float As[64*68];
    __shared__ float Ws[64*68];
    __shared__ int   toks[64];
    int r0 = blockIdx.x * 64;
    int d0 = blockIdx.y * 64;
    int tid = threadIdx.x;
    int tx4 = (tid & 15) * 4, ty4 = (tid >> 4) * 4;

    if (tid < 64) {
        int r = r0 + tid, t = r >> 6, b = r & 63;
        toks[tid] = x[b*Tn + t];
    }
    __syncthreads();

    float acc[4][4];
    {
        float4 bias = *(const float4*)&bh[d0 + tx4];
#pragma unroll
        for (int ii = 0; ii < 4; ii++) {
            acc[ii][0] = bias.x; acc[ii][1] = bias.y;
            acc[ii][2] = bias.z; acc[ii][3] = bias.w;
        }
    }

    for (int k0 = 0; k0 < En; k0 += 64) {
#pragma unroll
        for (int s = 0; s < 16; s++) {
            int idx = tid + s*256;
            int ee = idx & 63, i = idx >> 6;
            As[ee*68 + i] = embed[toks[i]*En + k0 + ee];
            int dd = idx & 63, kw = idx >> 6;
            Ws[kw*68 + dd] = Wih[(k0+kw)*Dn + d0 + dd];
        }
        __syncthreads();
        GEMM_CORE(64)
        __syncthreads();
    }
#pragma unroll
    for (int ii = 0; ii < 4; ii++) {
        float4 o = make_float4(acc[ii][0], acc[ii][1], acc[ii][2], acc[ii][3]);
        *(float4*)&g_xp[(r0 + ty4 + ii)*Dn + d0 + tx4] = o;
    }
}

// ---------------------------------------------------------------------------
// 2) Recurrence: h_t = tanh(xp_t + h_{t-1} @ W_hh), one CTA per batch row.
//    (unchanged — latency-floor bound within its single CTA/SM)
__global__ void __launch_bounds__(256, 1) k_rnn() {
    extern __shared__ float sm[];
    float*  hs = sm;                         // 256 floats
    float4* Ws = (float4*)(sm + 256);        // [32][256] float4 = 128 KB
    int b = blockIdx.x, d = threadIdx.x;

    const float* wtrow = &g_Wt[d*Dn];
    float4 wreg[32];
#pragma unroll
    for (int i = 0; i < 32; i++) wreg[i] = *(const float4*)(wtrow + 4*i);
#pragma unroll
    for (int i = 0; i < 32; i++) Ws[i*256 + d] = *(const float4*)(wtrow + 128 + 4*i);
    hs[d] = 0.f;
    __syncthreads();

    for (int t = 0; t < Tn; t++) {
        float acc  = g_xp[(t*Bn + b)*Dn + d];
        float acc2 = 0.f;
#pragma unroll
        for (int i = 0; i < 32; i++) {
            float4 h = *(const float4*)&hs[4*i];
            acc = fmaf(wreg[i].x, h.x, acc); acc = fmaf(wreg[i].y, h.y, acc);
            acc = fmaf(wreg[i].z, h.z, acc); acc = fmaf(wreg[i].w, h.w, acc);
        }
#pragma unroll
        for (int i = 0; i < 32; i++) {
            float4 w = Ws[i*256 + d];
            float4 h = *(const float4*)&hs[128 + 4*i];
            acc2 = fmaf(w.x, h.x, acc2); acc2 = fmaf(w.y, h.y, acc2);
            acc2 = fmaf(w.z, h.z, acc2); acc2 = fmaf(w.w, h.w, acc2);
        }
        float hv = tanhf(acc + acc2);        // accurate tanh: errors compound here
        __syncthreads();
        hs[d] = hv;
        g_H[(t*Bn + b)*Dn + d] = hv;
        __syncthreads();
    }
}

// ---------------------------------------------------------------------------
// 3) P = H @ W_attn (z=0), C = H @ U_attn (z=1).  M=32768,N=256,K=256.
//    grid(512, 4, 2)
__global__ void __launch_bounds__(256, 4) k_proj(
    const float* __restrict__ Wa, const float* __restrict__ Ua)
{
    __shared__ float As[64*68];
    __shared__ float Ws[64*68];
    int r0 = blockIdx.x * 64;
    int d0 = blockIdx.y * 64;
    int tid = threadIdx.x;
    int tx4 = (tid & 15) * 4, ty4 = (tid >> 4) * 4;
    const float* Wsel = blockIdx.z ? Ua : Wa;
    float*       Out  = blockIdx.z ? g_C : g_P;

    float acc[4][4];
#pragma unroll
    for (int ii = 0; ii < 4; ii++)
#pragma unroll
        for (int jj = 0; jj < 4; jj++) acc[ii][jj] = 0.f;

    for (int k0 = 0; k0 < Dn; k0 += 64) {
#pragma unroll
        for (int s = 0; s < 16; s++) {
            int idx = tid + s*256;
            int kk = idx & 63, i = idx >> 6;
            As[kk*68 + i] = g_H[(r0+i)*Dn + k0 + kk];
            int dd = idx & 63, kw = idx >> 6;
            Ws[kw*68 + dd] = Wsel[(k0+kw)*Dn + d0 + dd];
        }
        __syncthreads();
        GEMM_CORE(64)
        __syncthreads();
    }
#pragma unroll
    for (int ii = 0; ii < 4; ii++) {
        float4 o = make_float4(acc[ii][0], acc[ii][1], acc[ii][2], acc[ii][3]);
        *(float4*)&Out[(r0 + ty4 + ii)*Dn + d0 + tx4] = o;
    }
}

// ---------------------------------------------------------------------------
// 4) Bahdanau attention, tiled: block = (b, 16 queries).  (unchanged — passed)
__global__ void __launch_bounds__(256) k_attn(const float* __restrict__ vat) {
    __shared__ float Cs[TT][Dn - 4];         // columns 0..251
    __shared__ float Cs2[TT][4];             // remainder columns 252..255
    __shared__ float EsT[Tn][TT];            // 32 KB  (transposed: [tp][tq])
    int b  = blockIdx.y;
    int t0 = blockIdx.x * TT;
    int tid = threadIdx.x;
    int warp = tid >> 5, lane = tid & 31;

    for (int idx = tid; idx < TT*Dn; idx += 256) {
        int q = idx / Dn, d2 = idx % Dn;
        float v = g_C[((t0+q)*Bn + b)*Dn + d2];
        if (d2 < Dn - 4) Cs[q][d2] = v; else Cs2[q][d2 - (Dn-4)] = v;
    }
    float vreg[8];
#pragma unroll
    for (int j = 0; j < 8; j++) vreg[j] = vat[lane + 32*j];
    __syncthreads();

    int t_hi = t0 + TT;
    // Pass 1: energies (MUFU-bound). Warp handles one key tp at a time.
    for (int tp = warp; tp < t_hi; tp += 8) {
        float p[8];
#pragma unroll
        for (int j = 0; j < 8; j++) p[j] = g_P[(tp*Bn + b)*Dn + lane + 32*j];
#pragma unroll
        for (int q = 0; q < TT; q++) {
            float s = 0.f;
#pragma unroll
            for (int j = 0; j < 8; j++) {
                int d2 = lane + 32*j;
                float cv = (d2 < Dn - 4) ? Cs[q][d2] : Cs2[q][d2 - (Dn-4)];
                float z = p[j] + cv;
                float th; asm("tanh.approx.f32 %0, %1;" : "=f"(th) : "f"(z));
                s = fmaf(vreg[j], th, s);
            }
#pragma unroll
            for (int o = 16; o; o >>= 1) s += __shfl_xor_sync(0xffffffffu, s, o);
            if (lane == 0) EsT[tp][q] = s;
        }
    }
    __syncthreads();

    // Pass 2: masked softmax per query (weights stored back, zeros for tp>=tq)
    for (int q = warp; q < TT; q += 8) {
        int tg = t0 + q;
        float mx = -3.4e38f;
        for (int tp = lane; tp < tg; tp += 32) mx = fmaxf(mx, EsT[tp][q]);
#pragma unroll
        for (int o = 16; o; o >>= 1) mx = fmaxf(mx, __shfl_xor_sync(0xffffffffu, mx, o));
        float sum = 0.f;
        for (int tp = lane; tp < tg; tp += 32) {
            float e = __expf(EsT[tp][q] - mx);
            EsT[tp][q] = e; sum += e;
        }
#pragma unroll
        for (int o = 16; o; o >>= 1) sum += __shfl_xor_sync(0xffffffffu, sum, o);
        float inv = tg > 0 ? 1.f / sum : 0.f;
        for (int tp = lane; tp < t_hi; tp += 32) {
            float wv = (tp < tg) ? EsT[tp][q] * inv : 0.f;
            EsT[tp][q] = wv;
        }
    }
    __syncthreads();

    // Pass 3: ctx[q][d] = sum_tp w * H[tp][b][d]  (float4 weight broadcast)
    int d = tid;
    float acc[TT];
#pragma unroll
    for (int q = 0; q < TT; q++) acc[q] = 0.f;
    int tmax = t0 + TT - 1;                  // max key index needed
    for (int tp = 0; tp < tmax; tp++) {
        float hval = g_H[(tp*Bn + b)*Dn + d];
#pragma unroll
        for (int q = 0; q < TT; q += 4) {
            float4 w = *(const float4*)&EsT[tp][q];
            acc[q]   = fmaf(w.x, hval, acc[q]);
            acc[q+1] = fmaf(w.y, hval, acc[q+1]);
            acc[q+2] = fmaf(w.z, hval, acc[q+2]);
            acc[q+3] = fmaf(w.w, hval, acc[q+3]);
        }
    }
#pragma unroll
    for (int q = 0; q < TT; q++) {
        int tg = t0 + q;
        float c = acc[q];
        if (tg == 0) c = g_H[b*Dn + d];      // t==0: ctx = h itself
        g_CTX[(tg*Bn + b)*Dn + d] = c;
    }
}

// ---------------------------------------------------------------------------
// 5) logits = [H | CTX] @ fc_W + fc_b.  M=32768, N=512, K=512. grid(512,8)
//    K-tiles 0..3 read H, 4..7 read CTX (pointer select per tile).
__global__ void __launch_bounds__(256, 4) k_logits(
    const float* __restrict__ fcW, const float* __restrict__ fcb,
    float* __restrict__ out)
{
    __shared__ float As[64*68];
    __shared__ float Ws[64*68];
    int r0 = blockIdx.x * 64;
    int d0 = blockIdx.y * 64;
    int tid = threadIdx.x;
    int tx4 = (tid & 15) * 4, ty4 = (tid >> 4) * 4;

    float acc[4][4];
    {
        float4 bias = *(const float4*)&fcb[d0 + tx4];
#pragma unroll
        for (int ii = 0; ii < 4; ii++) {
            acc[ii][0] = bias.x; acc[ii][1] = bias.y;
            acc[ii][2] = bias.z; acc[ii][3] = bias.w;
        }
    }

    for (int kt = 0; kt < 8; kt++) {
        int k0 = kt * 64;
        const float* src = (kt < 4) ? g_H : g_CTX;
        int ksrc = k0 & (Dn - 1);
#pragma unroll
        for (int s = 0; s < 16; s++) {
            int idx = tid + s*256;
            int kk = idx & 63, i = idx >> 6;
            As[kk*68 + i] = src[(r0+i)*Dn + ksrc + kk];
            int dd = idx & 63, kw = idx >> 6;
            Ws[kw*68 + dd] = fcW[(k0+kw)*Vn + d0 + dd];
        }
        __syncthreads();
        GEMM_CORE(64)
        __syncthreads();
    }
#pragma unroll
    for (int ii = 0; ii < 4; ii++) {
        int r = r0 + ty4 + ii, t = r >> 6, b = r & 63;
        float4 o = make_float4(acc[ii][0], acc[ii][1], acc[ii][2], acc[ii][3]);
        *(float4*)&out[(b*Tn + t)*Vn + d0 + tx4] = o;
    }
}

// ---------------------------------------------------------------------------
extern "C" void kernel_launch(void* const* d_in, const int* in_sizes, int n_in,
                              void* d_out, int out_size)
{
    const int*   x     = (const int*)  d_in[0];
    const float* embed = (const float*)d_in[1];
    const float* Wih   = (const float*)d_in[2];
    const float* Whh   = (const float*)d_in[3];
    const float* bh    = (const float*)d_in[4];
    const float* Wat   = (const float*)d_in[5];
    const float* Uat   = (const float*)d_in[6];
    const float* vat   = (const float*)d_in[7];
    const float* fcW   = (const float*)d_in[8];
    const float* fcb   = (const float*)d_in[9];
    float* out = (float*)d_out;

    cudaFuncSetAttribute(k_rnn, cudaFuncAttributeMaxDynamicSharedMemorySize, 256*4 + 32*256*16);

    k_transpose<<<Dn, Dn>>>(Whh);
    k_embed<<<dim3((Tn*Bn)/64, Dn/64), 256>>>(x, embed, Wih, bh);
    k_rnn<<<Bn, 256, 256*4 + 32*256*16>>>();
    k_proj<<<dim3((Tn*Bn)/64, Dn/64, 2), 256>>>(Wat, Uat);
    k_attn<<<dim3(Tn/TT, Bn), 256>>>(vat);
    k_logits<<<dim3((Tn*Bn)/64, Vn/64), 256>>>(fcW, fcb, out);
}

// round 8
// speedup vs baseline: 1.2381x; 1.0721x over previous
#include <cuda_runtime.h>
#include <math.h>

// Problem dims (fixed by the reference): B=64, T=512, V=512, E=128, D=256
constexpr int Tn = 512, Bn = 64, Vn = 512, En = 128, Dn = 256;
constexpr int TT = 16;   // query-tile for attention

typedef unsigned long long u64;

// Scratch (device globals: allocation-free rule)
__device__ float g_xp [Tn*Bn*Dn];   // input projection  [t][b][d]
__device__ float g_H  [Tn*Bn*Dn];   // hidden states     [t][b][d]
__device__ float g_P  [Tn*Bn*Dn];   // H @ W_attn        [t][b][d]
__device__ float g_C  [Tn*Bn*Dn];   // H @ U_attn        [t][b][d]
__device__ float g_CTX[Tn*Bn*Dn];   // attention context [t][b][d]
__device__ float g_Wt [Dn*Dn];      // W_hh transposed: g_Wt[d*Dn+k] = W_hh[k][d]

// packed f32x2 ops
#define FMA2(acc, a, w) \
    asm("fma.rn.f32x2 %0, %1, %2, %0;" : "+l"(acc) : "l"(a), "l"(w))
#define DUP2(dst, s) \
    asm("mov.b64 %0, {%1, %1};" : "=l"(dst) : "r"(s))

// ---------------------------------------------------------------------------
// 0) transpose W_hh (one-time tiny cost per call)
__global__ void k_transpose(const float* __restrict__ W) {
    int k = blockIdx.x, d = threadIdx.x;
    g_Wt[d*Dn + k] = W[k*Dn + d];
}

// ===========================================================================
// 128x128 GEMM tile core, KT=32 k-slab. 256 thr = 16x16, each 8x8 outputs.
// Accumulators packed along N: accp[ii][jp] = (C[ii][2jp], C[ii][2jp+1]).
// Per k: 4 LDS.128 + 8 dup-mov + 32 FFMA2(=64 MACs).  FMA2-pipe bound.
//   As[kk*132 + i]  : A^T slab (row kk, 128 i's + pad)
//   Ws[kk*132 + dd] : W slab
// ===========================================================================
__device__ __forceinline__ void gemm_core32(
    const float* As, const float* Ws, u64 accp[8][4], int ty8, int tx8)
{
#pragma unroll 8
    for (int kk = 0; kk < 32; kk++) {
        float4 a0 = *(const float4*)&As[kk*132 + ty8];
        float4 a1 = *(const float4*)&As[kk*132 + ty8 + 4];
        ulonglong2 w01 = *(const ulonglong2*)&Ws[kk*132 + tx8];
        ulonglong2 w23 = *(const ulonglong2*)&Ws[kk*132 + tx8 + 4];
        u64 wp0 = w01.x, wp1 = w01.y, wp2 = w23.x, wp3 = w23.y;
        u64 ad[8];
        DUP2(ad[0], __float_as_uint(a0.x));
        DUP2(ad[1], __float_as_uint(a0.y));
        DUP2(ad[2], __float_as_uint(a0.z));
        DUP2(ad[3], __float_as_uint(a0.w));
        DUP2(ad[4], __float_as_uint(a1.x));
        DUP2(ad[5], __float_as_uint(a1.y));
        DUP2(ad[6], __float_as_uint(a1.z));
        DUP2(ad[7], __float_as_uint(a1.w));
#pragma unroll
        for (int ii = 0; ii < 8; ii++) {
            FMA2(accp[ii][0], ad[ii], wp0);
            FMA2(accp[ii][1], ad[ii], wp1);
            FMA2(accp[ii][2], ad[ii], wp2);
            FMA2(accp[ii][3], ad[ii], wp3);
        }
    }
}

// ---------------------------------------------------------------------------
// 1) xp = embed[x] @ W_ih + b_h.   M=32768, N=256, K=128. grid(256,2)
__global__ void __launch_bounds__(256, 2) k_embed(
    const int* __restrict__ x, const float* __restrict__ embed,
    const float* __restrict__ Wih, const float* __restrict__ bh)
{
    __shared__ float As[32*132];
    __shared__ float Ws[32*132];
    __shared__ int   toks[128];
    int r0 = blockIdx.x * 128;
    int d0 = blockIdx.y * 128;
    int tid = threadIdx.x;
    int tx8 = (tid & 15) * 8, ty8 = (tid >> 4) * 8;

    if (tid < 128) {
        int r = r0 + tid, t = r >> 6, b = r & 63;
        toks[tid] = x[b*Tn + t];
    }

    u64 accp[8][4];
    {
        ulonglong2 b01 = *(const ulonglong2*)&bh[d0 + tx8];
        ulonglong2 b23 = *(const ulonglong2*)&bh[d0 + tx8 + 4];
#pragma unroll
        for (int ii = 0; ii < 8; ii++) {
            accp[ii][0] = b01.x; accp[ii][1] = b01.y;
            accp[ii][2] = b23.x; accp[ii][3] = b23.y;
        }
    }
    __syncthreads();

    for (int k0 = 0; k0 < En; k0 += 32) {
#pragma unroll
        for (int s = 0; s < 16; s++) {
            int idx = tid + s*256;
            int kk = idx & 31, i = idx >> 5;
            As[kk*132 + i] = embed[toks[i]*En + k0 + kk];
            int dd = idx & 127, kw = idx >> 7;
            Ws[kw*132 + dd] = Wih[(k0+kw)*Dn + d0 + dd];
        }
        __syncthreads();
        gemm_core32(As, Ws, accp, ty8, tx8);
        __syncthreads();
    }
#pragma unroll
    for (int ii = 0; ii < 8; ii++) {
        float* row = &g_xp[(r0 + ty8 + ii)*Dn + d0 + tx8];
        ((ulonglong2*)row)[0] = make_ulonglong2(accp[ii][0], accp[ii][1]);
        ((ulonglong2*)row)[1] = make_ulonglong2(accp[ii][2], accp[ii][3]);
    }
}

// ---------------------------------------------------------------------------
// 2) Recurrence: h_t = tanh(xp_t + h_{t-1} @ W_hh), one CTA per batch row.
//    (unchanged — near its smem-crossbar floor)
__global__ void __launch_bounds__(256, 1) k_rnn() {
    extern __shared__ float sm[];
    float*  hs = sm;                         // 256 floats
    float4* Ws = (float4*)(sm + 256);        // [32][256] float4 = 128 KB
    int b = blockIdx.x, d = threadIdx.x;

    const float* wtrow = &g_Wt[d*Dn];
    float4 wreg[32];
#pragma unroll
    for (int i = 0; i < 32; i++) wreg[i] = *(const float4*)(wtrow + 4*i);
#pragma unroll
    for (int i = 0; i < 32; i++) Ws[i*256 + d] = *(const float4*)(wtrow + 128 + 4*i);
    hs[d] = 0.f;
    __syncthreads();

    for (int t = 0; t < Tn; t++) {
        float acc  = g_xp[(t*Bn + b)*Dn + d];
        float acc2 = 0.f;
#pragma unroll
        for (int i = 0; i < 32; i++) {
            float4 h = *(const float4*)&hs[4*i];
            acc = fmaf(wreg[i].x, h.x, acc); acc = fmaf(wreg[i].y, h.y, acc);
            acc = fmaf(wreg[i].z, h.z, acc); acc = fmaf(wreg[i].w, h.w, acc);
        }
#pragma unroll
        for (int i = 0; i < 32; i++) {
            float4 w = Ws[i*256 + d];
            float4 h = *(const float4*)&hs[128 + 4*i];
            acc2 = fmaf(w.x, h.x, acc2); acc2 = fmaf(w.y, h.y, acc2);
            acc2 = fmaf(w.z, h.z, acc2); acc2 = fmaf(w.w, h.w, acc2);
        }
        float hv = tanhf(acc + acc2);        // accurate tanh: errors compound here
        __syncthreads();
        hs[d] = hv;
        g_H[(t*Bn + b)*Dn + d] = hv;
        __syncthreads();
    }
}

// ---------------------------------------------------------------------------
// 3) P = H @ W_attn (z=0), C = H @ U_attn (z=1).  M=32768,N=256,K=256.
//    grid(256, 2, 2)
__global__ void __launch_bounds__(256, 2) k_proj(
    const float* __restrict__ Wa, const float* __restrict__ Ua)
{
    __shared__ float As[32*132];
    __shared__ float Ws[32*132];
    int r0 = blockIdx.x * 128;
    int d0 = blockIdx.y * 128;
    int tid = threadIdx.x;
    int tx8 = (tid & 15) * 8, ty8 = (tid >> 4) * 8;
    const float* Wsel = blockIdx.z ? Ua : Wa;
    float*       Out  = blockIdx.z ? g_C : g_P;

    u64 accp[8][4];
#pragma unroll
    for (int ii = 0; ii < 8; ii++)
#pragma unroll
        for (int jp = 0; jp < 4; jp++) accp[ii][jp] = 0ULL;

    for (int k0 = 0; k0 < Dn; k0 += 32) {
#pragma unroll
        for (int s = 0; s < 16; s++) {
            int idx = tid + s*256;
            int kk = idx & 31, i = idx >> 5;
            As[kk*132 + i] = g_H[(r0+i)*Dn + k0 + kk];
            int dd = idx & 127, kw = idx >> 7;
            Ws[kw*132 + dd] = Wsel[(k0+kw)*Dn + d0 + dd];
        }
        __syncthreads();
        gemm_core32(As, Ws, accp, ty8, tx8);
        __syncthreads();
    }
#pragma unroll
    for (int ii = 0; ii < 8; ii++) {
        float* row = &Out[(r0 + ty8 + ii)*Dn + d0 + tx8];
        ((ulonglong2*)row)[0] = make_ulonglong2(accp[ii][0], accp[ii][1]);
        ((ulonglong2*)row)[1] = make_ulonglong2(accp[ii][2], accp[ii][3]);
    }
}

// ---------------------------------------------------------------------------
// 4) Bahdanau attention, tiled: block = (b, 16 queries).  (unchanged — MUFU floor)
__global__ void __launch_bounds__(256) k_attn(const float* __restrict__ vat) {
    __shared__ float Cs[TT][Dn - 4];         // columns 0..251
    __shared__ float Cs2[TT][4];             // remainder columns 252..255
    __shared__ float EsT[Tn][TT];            // 32 KB  (transposed: [tp][tq])
    int b  = blockIdx.y;
    int t0 = blockIdx.x * TT;
    int tid = threadIdx.x;
    int warp = tid >> 5, lane = tid & 31;

    for (int idx = tid; idx < TT*Dn; idx += 256) {
        int q = idx / Dn, d2 = idx % Dn;
        float v = g_C[((t0+q)*Bn + b)*Dn + d2];
        if (d2 < Dn - 4) Cs[q][d2] = v; else Cs2[q][d2 - (Dn-4)] = v;
    }
    float vreg[8];
#pragma unroll
    for (int j = 0; j < 8; j++) vreg[j] = vat[lane + 32*j];
    __syncthreads();

    int t_hi = t0 + TT;
    // Pass 1: energies (MUFU-bound). Warp handles one key tp at a time.
    for (int tp = warp; tp < t_hi; tp += 8) {
        float p[8];
#pragma unroll
        for (int j = 0; j < 8; j++) p[j] = g_P[(tp*Bn + b)*Dn + lane + 32*j];
#pragma unroll
        for (int q = 0; q < TT; q++) {
            float s = 0.f;
#pragma unroll
            for (int j = 0; j < 8; j++) {
                int d2 = lane + 32*j;
                float cv = (d2 < Dn - 4) ? Cs[q][d2] : Cs2[q][d2 - (Dn-4)];
                float z = p[j] + cv;
                float th; asm("tanh.approx.f32 %0, %1;" : "=f"(th) : "f"(z));
                s = fmaf(vreg[j], th, s);
            }
#pragma unroll
            for (int o = 16; o; o >>= 1) s += __shfl_xor_sync(0xffffffffu, s, o);
            if (lane == 0) EsT[tp][q] = s;
        }
    }
    __syncthreads();

    // Pass 2: masked softmax per query (weights stored back, zeros for tp>=tq)
    for (int q = warp; q < TT; q += 8) {
        int tg = t0 + q;
        float mx = -3.4e38f;
        for (int tp = lane; tp < tg; tp += 32) mx = fmaxf(mx, EsT[tp][q]);
#pragma unroll
        for (int o = 16; o; o >>= 1) mx = fmaxf(mx, __shfl_xor_sync(0xffffffffu, mx, o));
        float sum = 0.f;
        for (int tp = lane; tp < tg; tp += 32) {
            float e = __expf(EsT[tp][q] - mx);
            EsT[tp][q] = e; sum += e;
        }
#pragma unroll
        for (int o = 16; o; o >>= 1) sum += __shfl_xor_sync(0xffffffffu, sum, o);
        float inv = tg > 0 ? 1.f / sum : 0.f;
        for (int tp = lane; tp < t_hi; tp += 32) {
            float wv = (tp < tg) ? EsT[tp][q] * inv : 0.f;
            EsT[tp][q] = wv;
        }
    }
    __syncthreads();

    // Pass 3: ctx[q][d] = sum_tp w * H[tp][b][d]  (float4 weight broadcast)
    int d = tid;
    float acc[TT];
#pragma unroll
    for (int q = 0; q < TT; q++) acc[q] = 0.f;
    int tmax = t0 + TT - 1;                  // max key index needed
    for (int tp = 0; tp < tmax; tp++) {
        float hval = g_H[(tp*Bn + b)*Dn + d];
#pragma unroll
        for (int q = 0; q < TT; q += 4) {
            float4 w = *(const float4*)&EsT[tp][q];
            acc[q]   = fmaf(w.x, hval, acc[q]);
            acc[q+1] = fmaf(w.y, hval, acc[q+1]);
            acc[q+2] = fmaf(w.z, hval, acc[q+2]);
            acc[q+3] = fmaf(w.w, hval, acc[q+3]);
        }
    }
#pragma unroll
    for (int q = 0; q < TT; q++) {
        int tg = t0 + q;
        float c = acc[q];
        if (tg == 0) c = g_H[b*Dn + d];      // t==0: ctx = h itself
        g_CTX[(tg*Bn + b)*Dn + d] = c;
    }
}

// ---------------------------------------------------------------------------
// 5) logits = [H | CTX] @ fc_W + fc_b.  M=32768, N=512, K=512. grid(256,4)
//    K-slabs 0..7 read H, 8..15 read CTX.
__global__ void __launch_bounds__(256, 2) k_logits(
    const float* __restrict__ fcW, const float* __restrict__ fcb,
    float* __restrict__ out)
{
    __shared__ float As[32*132];
    __shared__ float Ws[32*132];
    int r0 = blockIdx.x * 128;
    int d0 = blockIdx.y * 128;
    int tid = threadIdx.x;
    int tx8 = (tid & 15) * 8, ty8 = (tid >> 4) * 8;

    u64 accp[8][4];
    {
        ulonglong2 b01 = *(const ulonglong2*)&fcb[d0 + tx8];
        ulonglong2 b23 = *(const ulonglong2*)&fcb[d0 + tx8 + 4];
#pragma unroll
        for (int ii = 0; ii < 8; ii++) {
            accp[ii][0] = b01.x; accp[ii][1] = b01.y;
            accp[ii][2] = b23.x; accp[ii][3] = b23.y;
        }
    }

    for (int kt = 0; kt < 16; kt++) {
        int k0 = kt * 32;
        const float* src = (kt < 8) ? g_H : g_CTX;
        int ksrc = k0 & (Dn - 1);
#pragma unroll
        for (int s = 0; s < 16; s++) {
            int idx = tid + s*256;
            int kk = idx & 31, i = idx >> 5;
            As[kk*132 + i] = src[(r0+i)*Dn + ksrc + kk];
            int dd = idx & 127, kw = idx >> 7;
            Ws[kw*132 + dd] = fcW[(k0+kw)*Vn + d0 + dd];
        }
        __syncthreads();
        gemm_core32(As, Ws, accp, ty8, tx8);
        __syncthreads();
    }
#pragma unroll
    for (int ii = 0; ii < 8; ii++) {
        int r = r0 + ty8 + ii, t = r >> 6, b = r & 63;
        float* row = &out[(b*Tn + t)*Vn + d0 + tx8];
        ((ulonglong2*)row)[0] = make_ulonglong2(accp[ii][0], accp[ii][1]);
        ((ulonglong2*)row)[1] = make_ulonglong2(accp[ii][2], accp[ii][3]);
    }
}

// ---------------------------------------------------------------------------
extern "C" void kernel_launch(void* const* d_in, const int* in_sizes, int n_in,
                              void* d_out, int out_size)
{
    const int*   x     = (const int*)  d_in[0];
    const float* embed = (const float*)d_in[1];
    const float* Wih   = (const float*)d_in[2];
    const float* Whh   = (const float*)d_in[3];
    const float* bh    = (const float*)d_in[4];
    const float* Wat   = (const float*)d_in[5];
    const float* Uat   = (const float*)d_in[6];
    const float* vat   = (const float*)d_in[7];
    const float* fcW   = (const float*)d_in[8];
    const float* fcb   = (const float*)d_in[9];
    float* out = (float*)d_out;

    cudaFuncSetAttribute(k_rnn, cudaFuncAttributeMaxDynamicSharedMemorySize, 256*4 + 32*256*16);

    k_transpose<<<Dn, Dn>>>(Whh);
    k_embed<<<dim3((Tn*Bn)/128, Dn/128), 256>>>(x, embed, Wih, bh);
    k_rnn<<<Bn, 256, 256*4 + 32*256*16>>>();
    k_proj<<<dim3((Tn*Bn)/128, Dn/128, 2), 256>>>(Wat, Uat);
    k_attn<<<dim3(Tn/TT, Bn), 256>>>(vat);
    k_logits<<<dim3((Tn*Bn)/128, Vn/128), 256>>>(fcW, fcb, out);
}

// round 9
// speedup vs baseline: 1.2589x; 1.0168x over previous
#include <cuda_runtime.h>
#include <math.h>

// Problem dims (fixed by the reference): B=64, T=512, V=512, E=128, D=256
constexpr int Tn = 512, Bn = 64, Vn = 512, En = 128, Dn = 256;
constexpr int TT = 16;   // query-tile for attention

typedef unsigned long long u64;

// Scratch (device globals: allocation-free rule)
__device__ float g_xp [Tn*Bn*Dn];   // input projection  [t][b][d]
__device__ float g_H  [Tn*Bn*Dn];   // hidden states     [t][b][d]
__device__ float g_P  [Tn*Bn*Dn];   // H @ W_attn        [t][b][d]
__device__ float g_C  [Tn*Bn*Dn];   // H @ U_attn        [t][b][d]
__device__ float g_CTX[Tn*Bn*Dn];   // attention context [t][b][d]
__device__ float g_Wt [Dn*Dn];      // W_hh transposed

// packed f32x2 ops
#define FMA2(acc, a, w) \
    asm("fma.rn.f32x2 %0, %1, %2, %0;" : "+l"(acc) : "l"(a), "l"(w))
#define DUP2(dst, s) \
    asm("mov.b64 %0, {%1, %1};" : "=l"(dst) : "r"(s))

// cp.async helpers
__device__ __forceinline__ unsigned sm_u32(const void* p) {
    return (unsigned)__cvta_generic_to_shared(p);
}
#define CP4(dst, src)  asm volatile("cp.async.ca.shared.global [%0], [%1], 4;"  :: "r"(dst), "l"(src))
#define CP16(dst, src) asm volatile("cp.async.ca.shared.global [%0], [%1], 16;" :: "r"(dst), "l"(src))
#define CP_COMMIT()    asm volatile("cp.async.commit_group;")
#define CP_WAIT0()     asm volatile("cp.async.wait_group 0;")

// slab geometry: 128x128 CTA tile, K-slab 32, padded pitch 132
constexpr int SLAB = 32*132;                 // floats per tile buffer
constexpr int GEMM_SMEM = 4*SLAB*4;          // 2 x (As+Ws) = 67584 B

// ---------------------------------------------------------------------------
// 0) transpose W_hh (one-time tiny cost per call)
__global__ void k_transpose(const float* __restrict__ W) {
    int k = blockIdx.x, d = threadIdx.x;
    g_Wt[d*Dn + k] = W[k*Dn + d];
}

// ===========================================================================
// 128x128 GEMM tile core over one 32-k slab. 256 thr = 16x16, each 8x8.
// Accumulators packed along N. Per k: 4 LDS.128 + 8 dup + 32 FFMA2 (64 MACs).
// ===========================================================================
__device__ __forceinline__ void gemm_core32(
    const float* As, const float* Ws, u64 accp[8][4], int ty8, int tx8)
{
#pragma unroll 8
    for (int kk = 0; kk < 32; kk++) {
        float4 a0 = *(const float4*)&As[kk*132 + ty8];
        float4 a1 = *(const float4*)&As[kk*132 + ty8 + 4];
        ulonglong2 w01 = *(const ulonglong2*)&Ws[kk*132 + tx8];
        ulonglong2 w23 = *(const ulonglong2*)&Ws[kk*132 + tx8 + 4];
        u64 wp0 = w01.x, wp1 = w01.y, wp2 = w23.x, wp3 = w23.y;
        u64 ad[8];
        DUP2(ad[0], __float_as_uint(a0.x));
        DUP2(ad[1], __float_as_uint(a0.y));
        DUP2(ad[2], __float_as_uint(a0.z));
        DUP2(ad[3], __float_as_uint(a0.w));
        DUP2(ad[4], __float_as_uint(a1.x));
        DUP2(ad[5], __float_as_uint(a1.y));
        DUP2(ad[6], __float_as_uint(a1.z));
        DUP2(ad[7], __float_as_uint(a1.w));
#pragma unroll
        for (int ii = 0; ii < 8; ii++) {
            FMA2(accp[ii][0], ad[ii], wp0);
            FMA2(accp[ii][1], ad[ii], wp1);
            FMA2(accp[ii][2], ad[ii], wp2);
            FMA2(accp[ii][3], ad[ii], wp3);
        }
    }
}

// Async slab loaders. A: 4096 x 4B, kk-fastest (gmem-coalesced, 4-way STS ok).
// W: 1024 x 16B (both sides coalesced/conflict-free).
__device__ __forceinline__ void load_A_rows(
    unsigned as_b, const float* __restrict__ src, int r0, int k0, int tid)
{
#pragma unroll
    for (int s2 = 0; s2 < 16; s2++) {
        int idx = tid + s2*256;
        int kk = idx & 31, i = idx >> 5;
        CP4(as_b + (unsigned)(kk*132 + i)*4u, &src[(r0+i)*Dn + k0 + kk]);
    }
}
__device__ __forceinline__ void load_W(
    unsigned ws_b, const float* __restrict__ W, int ldw, int k0, int d0, int tid)
{
#pragma unroll
    for (int s2 = 0; s2 < 4; s2++) {
        int idx = tid + s2*256;
        int dq = idx & 31, kw = idx >> 5;
        CP16(ws_b + (unsigned)(kw*132 + 4*dq)*4u, &W[(k0+kw)*ldw + d0 + 4*dq]);
    }
}

// ---------------------------------------------------------------------------
// 1) xp = embed[x] @ W_ih + b_h.   M=32768, N=256, K=128. grid(256,2)
__global__ void __launch_bounds__(256, 2) k_embed(
    const int* __restrict__ x, const float* __restrict__ embed,
    const float* __restrict__ Wih, const float* __restrict__ bh)
{
    extern __shared__ float dyn[];
    float* bufA[2] = { dyn,          dyn + 2*SLAB };
    float* bufW[2] = { dyn + SLAB,   dyn + 3*SLAB };
    __shared__ int toks[128];
    int r0 = blockIdx.x * 128;
    int d0 = blockIdx.y * 128;
    int tid = threadIdx.x;
    int tx8 = (tid & 15) * 8, ty8 = (tid >> 4) * 8;

    if (tid < 128) {
        int r = r0 + tid, t = r >> 6, b = r & 63;
        toks[tid] = x[b*Tn + t];
    }
    __syncthreads();

    u64 accp[8][4];
    {
        ulonglong2 b01 = *(const ulonglong2*)&bh[d0 + tx8];
        ulonglong2 b23 = *(const ulonglong2*)&bh[d0 + tx8 + 4];
#pragma unroll
        for (int ii = 0; ii < 8; ii++) {
            accp[ii][0] = b01.x; accp[ii][1] = b01.y;
            accp[ii][2] = b23.x; accp[ii][3] = b23.y;
        }
    }

    // gathered A loader (token rows)
    auto loadA = [&](unsigned as_b, int k0) {
#pragma unroll
        for (int s2 = 0; s2 < 16; s2++) {
            int idx = tid + s2*256;
            int kk = idx & 31, i = idx >> 5;
            CP4(as_b + (unsigned)(kk*132 + i)*4u, &embed[toks[i]*En + k0 + kk]);
        }
    };

    constexpr int S = En/32;   // 4
    loadA(sm_u32(bufA[0]), 0);
    load_W(sm_u32(bufW[0]), Wih, Dn, 0, d0, tid);
    CP_COMMIT();
    for (int kt = 0; kt < S; kt++) {
        CP_WAIT0();
        __syncthreads();
        if (kt + 1 < S) {
            int nb = (kt+1) & 1;
            loadA(sm_u32(bufA[nb]), (kt+1)*32);
            load_W(sm_u32(bufW[nb]), Wih, Dn, (kt+1)*32, d0, tid);
            CP_COMMIT();
        }
        gemm_core32(bufA[kt&1], bufW[kt&1], accp, ty8, tx8);
    }
#pragma unroll
    for (int ii = 0; ii < 8; ii++) {
        float* row = &g_xp[(r0 + ty8 + ii)*Dn + d0 + tx8];
        ((ulonglong2*)row)[0] = make_ulonglong2(accp[ii][0], accp[ii][1]);
        ((ulonglong2*)row)[1] = make_ulonglong2(accp[ii][2], accp[ii][3]);
    }
}

// ---------------------------------------------------------------------------
// 2) Recurrence: h_t = tanh(xp_t + h_{t-1} @ W_hh), one CTA per batch row.
//    4-way split accumulation chains + double-buffered h (1 barrier/step).
__global__ void __launch_bounds__(256, 1) k_rnn() {
    extern __shared__ float sm[];
    float*  hbuf = sm;                       // 2 x 256
    float4* Ws   = (float4*)(sm + 512);      // [32][256] float4 = 128 KB
    int b = blockIdx.x, d = threadIdx.x;

    const float* wtrow = &g_Wt[d*Dn];
    float4 wreg[32];
#pragma unroll
    for (int i = 0; i < 32; i++) wreg[i] = *(const float4*)(wtrow + 4*i);
#pragma unroll
    for (int i = 0; i < 32; i++) Ws[i*256 + d] = *(const float4*)(wtrow + 128 + 4*i);
    hbuf[d] = 0.f; hbuf[256 + d] = 0.f;
    __syncthreads();

    for (int t = 0; t < Tn; t++) {
        const float* hp = hbuf + (t & 1) * 256;
        float*       hc = hbuf + ((t & 1) ^ 1) * 256;
        float a0 = g_xp[(t*Bn + b)*Dn + d], a1 = 0.f, a2 = 0.f, a3 = 0.f;
        float b0 = 0.f, b1 = 0.f, b2 = 0.f, b3 = 0.f;
#pragma unroll
        for (int i = 0; i < 32; i += 4) {
            float4 h0 = *(const float4*)&hp[4*i];
            a0 = fmaf(wreg[i].x, h0.x, a0); a0 = fmaf(wreg[i].y, h0.y, a0);
            a0 = fmaf(wreg[i].z, h0.z, a0); a0 = fmaf(wreg[i].w, h0.w, a0);
            float4 h1 = *(const float4*)&hp[4*(i+1)];
            a1 = fmaf(wreg[i+1].x, h1.x, a1); a1 = fmaf(wreg[i+1].y, h1.y, a1);
            a1 = fmaf(wreg[i+1].z, h1.z, a1); a1 = fmaf(wreg[i+1].w, h1.w, a1);
            float4 h2 = *(const float4*)&hp[4*(i+2)];
            a2 = fmaf(wreg[i+2].x, h2.x, a2); a2 = fmaf(wreg[i+2].y, h2.y, a2);
            a2 = fmaf(wreg[i+2].z, h2.z, a2); a2 = fmaf(wreg[i+2].w, h2.w, a2);
            float4 h3 = *(const float4*)&hp[4*(i+3)];
            a3 = fmaf(wreg[i+3].x, h3.x, a3); a3 = fmaf(wreg[i+3].y, h3.y, a3);
            a3 = fmaf(wreg[i+3].z, h3.z, a3); a3 = fmaf(wreg[i+3].w, h3.w, a3);
        }
#pragma unroll
        for (int i = 0; i < 32; i += 4) {
            float4 w0 = Ws[i*256 + d];
            float4 h0 = *(const float4*)&hp[128 + 4*i];
            b0 = fmaf(w0.x, h0.x, b0); b0 = fmaf(w0.y, h0.y, b0);
            b0 = fmaf(w0.z, h0.z, b0); b0 = fmaf(w0.w, h0.w, b0);
            float4 w1 = Ws[(i+1)*256 + d];
            float4 h1 = *(const float4*)&hp[128 + 4*(i+1)];
            b1 = fmaf(w1.x, h1.x, b1); b1 = fmaf(w1.y, h1.y, b1);
            b1 = fmaf(w1.z, h1.z, b1); b1 = fmaf(w1.w, h1.w, b1);
            float4 w2 = Ws[(i+2)*256 + d];
            float4 h2 = *(const float4*)&hp[128 + 4*(i+2)];
            b2 = fmaf(w2.x, h2.x, b2); b2 = fmaf(w2.y, h2.y, b2);
            b2 = fmaf(w2.z, h2.z, b2); b2 = fmaf(w2.w, h2.w, b2);
            float4 w3 = Ws[(i+3)*256 + d];
            float4 h3 = *(const float4*)&hp[128 + 4*(i+3)];
            b3 = fmaf(w3.x, h3.x, b3); b3 = fmaf(w3.y, h3.y, b3);
            b3 = fmaf(w3.z, h3.z, b3); b3 = fmaf(w3.w, h3.w, b3);
        }
        float hv = tanhf(((a0 + a1) + (a2 + a3)) + ((b0 + b1) + (b2 + b3)));
        hc[d] = hv;
        g_H[(t*Bn + b)*Dn + d] = hv;
        __syncthreads();
    }
}

// ---------------------------------------------------------------------------
// 3) P = H @ W_attn (z=0), C = H @ U_attn (z=1).  grid(256, 2, 2)
__global__ void __launch_bounds__(256, 2) k_proj(
    const float* __restrict__ Wa, const float* __restrict__ Ua)
{
    extern __shared__ float dyn[];
    float* bufA[2] = { dyn,          dyn + 2*SLAB };
    float* bufW[2] = { dyn + SLAB,   dyn + 3*SLAB };
    int r0 = blockIdx.x * 128;
    int d0 = blockIdx.y * 128;
    int tid = threadIdx.x;
    int tx8 = (tid & 15) * 8, ty8 = (tid >> 4) * 8;
    const float* Wsel = blockIdx.z ? Ua : Wa;
    float*       Out  = blockIdx.z ? g_C : g_P;

    u64 accp[8][4];
#pragma unroll
    for (int ii = 0; ii < 8; ii++)
#pragma unroll
        for (int jp = 0; jp < 4; jp++) accp[ii][jp] = 0ULL;

    constexpr int S = Dn/32;   // 8
    load_A_rows(sm_u32(bufA[0]), g_H, r0, 0, tid);
    load_W(sm_u32(bufW[0]), Wsel, Dn, 0, d0, tid);
    CP_COMMIT();
    for (int kt = 0; kt < S; kt++) {
        CP_WAIT0();
        __syncthreads();
        if (kt + 1 < S) {
            int nb = (kt+1) & 1;
            load_A_rows(sm_u32(bufA[nb]), g_H, r0, (kt+1)*32, tid);
            load_W(sm_u32(bufW[nb]), Wsel, Dn, (kt+1)*32, d0, tid);
            CP_COMMIT();
        }
        gemm_core32(bufA[kt&1], bufW[kt&1], accp, ty8, tx8);
    }
#pragma unroll
    for (int ii = 0; ii < 8; ii++) {
        float* row = &Out[(r0 + ty8 + ii)*Dn + d0 + tx8];
        ((ulonglong2*)row)[0] = make_ulonglong2(accp[ii][0], accp[ii][1]);
        ((ulonglong2*)row)[1] = make_ulonglong2(accp[ii][2], accp[ii][3]);
    }
}

// ---------------------------------------------------------------------------
// 4) Bahdanau attention, tiled: block = (b, 16 queries).  (unchanged — MUFU floor)
__global__ void __launch_bounds__(256) k_attn(const float* __restrict__ vat) {
    __shared__ float Cs[TT][Dn - 4];         // columns 0..251
    __shared__ float Cs2[TT][4];             // remainder columns 252..255
    __shared__ float EsT[Tn][TT];            // 32 KB  (transposed: [tp][tq])
    int b  = blockIdx.y;
    int t0 = blockIdx.x * TT;
    int tid = threadIdx.x;
    int warp = tid >> 5, lane = tid & 31;

    for (int idx = tid; idx < TT*Dn; idx += 256) {
        int q = idx / Dn, d2 = idx % Dn;
        float v = g_C[((t0+q)*Bn + b)*Dn + d2];
        if (d2 < Dn - 4) Cs[q][d2] = v; else Cs2[q][d2 - (Dn-4)] = v;
    }
    float vreg[8];
#pragma unroll
    for (int j = 0; j < 8; j++) vreg[j] = vat[lane + 32*j];
    __syncthreads();

    int t_hi = t0 + TT;
    // Pass 1: energies (MUFU-bound). Warp handles one key tp at a time.
    for (int tp = warp; tp < t_hi; tp += 8) {
        float p[8];
#pragma unroll
        for (int j = 0; j < 8; j++) p[j] = g_P[(tp*Bn + b)*Dn + lane + 32*j];
#pragma unroll
        for (int q = 0; q < TT; q++) {
            float s = 0.f;
#pragma unroll
            for (int j = 0; j < 8; j++) {
                int d2 = lane + 32*j;
                float cv = (d2 < Dn - 4) ? Cs[q][d2] : Cs2[q][d2 - (Dn-4)];
                float z = p[j] + cv;
                float th; asm("tanh.approx.f32 %0, %1;" : "=f"(th) : "f"(z));
                s = fmaf(vreg[j], th, s);
            }
#pragma unroll
            for (int o = 16; o; o >>= 1) s += __shfl_xor_sync(0xffffffffu, s, o);
            if (lane == 0) EsT[tp][q] = s;
        }
    }
    __syncthreads();

    // Pass 2: masked softmax per query (weights stored back, zeros for tp>=tq)
    for (int q = warp; q < TT; q += 8) {
        int tg = t0 + q;
        float mx = -3.4e38f;
        for (int tp = lane; tp < tg; tp += 32) mx = fmaxf(mx, EsT[tp][q]);
#pragma unroll
        for (int o = 16; o; o >>= 1) mx = fmaxf(mx, __shfl_xor_sync(0xffffffffu, mx, o));
        float sum = 0.f;
        for (int tp = lane; tp < tg; tp += 32) {
            float e = __expf(EsT[tp][q] - mx);
            EsT[tp][q] = e; sum += e;
        }
#pragma unroll
        for (int o = 16; o; o >>= 1) sum += __shfl_xor_sync(0xffffffffu, sum, o);
        float inv = tg > 0 ? 1.f / sum : 0.f;
        for (int tp = lane; tp < t_hi; tp += 32) {
            float wv = (tp < tg) ? EsT[tp][q] * inv : 0.f;
            EsT[tp][q] = wv;
        }
    }
    __syncthreads();

    // Pass 3: ctx[q][d] = sum_tp w * H[tp][b][d]  (float4 weight broadcast)
    int d = tid;
    float acc[TT];
#pragma unroll
    for (int q = 0; q < TT; q++) acc[q] = 0.f;
    int tmax = t0 + TT - 1;                  // max key index needed
    for (int tp = 0; tp < tmax; tp++) {
        float hval = g_H[(tp*Bn + b)*Dn + d];
#pragma unroll
        for (int q = 0; q < TT; q += 4) {
            float4 w = *(const float4*)&EsT[tp][q];
            acc[q]   = fmaf(w.x, hval, acc[q]);
            acc[q+1] = fmaf(w.y, hval, acc[q+1]);
            acc[q+2] = fmaf(w.z, hval, acc[q+2]);
            acc[q+3] = fmaf(w.w, hval, acc[q+3]);
        }
    }
#pragma unroll
    for (int q = 0; q < TT; q++) {
        int tg = t0 + q;
        float c = acc[q];
        if (tg == 0) c = g_H[b*Dn + d];      // t==0: ctx = h itself
        g_CTX[(tg*Bn + b)*Dn + d] = c;
    }
}

// ---------------------------------------------------------------------------
// 5) logits = [H | CTX] @ fc_W + fc_b.  M=32768, N=512, K=512. grid(256,4)
__global__ void __launch_bounds__(256, 2) k_logits(
    const float* __restrict__ fcW, const float* __restrict__ fcb,
    float* __restrict__ out)
{
    extern __shared__ float dyn[];
    float* bufA[2] = { dyn,          dyn + 2*SLAB };
    float* bufW[2] = { dyn + SLAB,   dyn + 3*SLAB };
    int r0 = blockIdx.x * 128;
    int d0 = blockIdx.y * 128;
    int tid = threadIdx.x;
    int tx8 = (tid & 15) * 8, ty8 = (tid >> 4) * 8;

    u64 accp[8][4];
    {
        ulonglong2 b01 = *(const ulonglong2*)&fcb[d0 + tx8];
        ulonglong2 b23 = *(const ulonglong2*)&fcb[d0 + tx8 + 4];
#pragma unroll
        for (int ii = 0; ii < 8; ii++) {
            accp[ii][0] = b01.x; accp[ii][1] = b01.y;
            accp[ii][2] = b23.x; accp[ii][3] = b23.y;
        }
    }

    constexpr int S = 16;   // K=512
    load_A_rows(sm_u32(bufA[0]), g_H, r0, 0, tid);
    load_W(sm_u32(bufW[0]), fcW, Vn, 0, d0, tid);
    CP_COMMIT();
    for (int kt = 0; kt < S; kt++) {
        CP_WAIT0();
        __syncthreads();
        if (kt + 1 < S) {
            int nb = (kt+1) & 1;
            int k1 = (kt+1) * 32;
            const float* src = (kt+1 < 8) ? g_H : g_CTX;
            load_A_rows(sm_u32(bufA[nb]), src, r0, k1 & (Dn-1), tid);
            load_W(sm_u32(bufW[nb]), fcW, Vn, k1, d0, tid);
            CP_COMMIT();
        }
        gemm_core32(bufA[kt&1], bufW[kt&1], accp, ty8, tx8);
    }
#pragma unroll
    for (int ii = 0; ii < 8; ii++) {
        int r = r0 + ty8 + ii, t = r >> 6, b = r & 63;
        float* row = &out[(b*Tn + t)*Vn + d0 + tx8];
        ((ulonglong2*)row)[0] = make_ulonglong2(accp[ii][0], accp[ii][1]);
        ((ulonglong2*)row)[1] = make_ulonglong2(accp[ii][2], accp[ii][3]);
    }
}

// ---------------------------------------------------------------------------
extern "C" void kernel_launch(void* const* d_in, const int* in_sizes, int n_in,
                              void* d_out, int out_size)
{
    const int*   x     = (const int*)  d_in[0];
    const float* embed = (const float*)d_in[1];
    const float* Wih   = (const float*)d_in[2];
    const float* Whh   = (const float*)d_in[3];
    const float* bh    = (const float*)d_in[4];
    const float* Wat   = (const float*)d_in[5];
    const float* Uat   = (const float*)d_in[6];
    const float* vat   = (const float*)d_in[7];
    const float* fcW   = (const float*)d_in[8];
    const float* fcb   = (const float*)d_in[9];
    float* out = (float*)d_out;

    cudaFuncSetAttribute(k_rnn,    cudaFuncAttributeMaxDynamicSharedMemorySize, 512*4 + 32*256*16);
    cudaFuncSetAttribute(k_embed,  cudaFuncAttributeMaxDynamicSharedMemorySize, GEMM_SMEM);
    cudaFuncSetAttribute(k_proj,   cudaFuncAttributeMaxDynamicSharedMemorySize, GEMM_SMEM);
    cudaFuncSetAttribute(k_logits, cudaFuncAttributeMaxDynamicSharedMemorySize, GEMM_SMEM);

    k_transpose<<<Dn, Dn>>>(Whh);
    k_embed<<<dim3((Tn*Bn)/128, Dn/128), 256, GEMM_SMEM>>>(x, embed, Wih, bh);
    k_rnn<<<Bn, 256, 512*4 + 32*256*16>>>();
    k_proj<<<dim3((Tn*Bn)/128, Dn/128, 2), 256, GEMM_SMEM>>>(Wat, Uat);
    k_attn<<<dim3(Tn/TT, Bn), 256>>>(vat);
    k_logits<<<dim3((Tn*Bn)/128, Vn/128), 256, GEMM_SMEM>>>(fcW, fcb, out);
}

// round 12
// speedup vs baseline: 1.4182x; 1.1266x over previous
#include <cuda_runtime.h>
#include <cuda_bf16.h>
#include <cstdint>
#include <math.h>

// Problem dims: B=64, T=512, V=512, E=128, D=256
constexpr int Tn = 512, Bn = 64, Vn = 512, En = 128, Dn = 256;
constexpr int TT = 16;

typedef unsigned long long u64;
typedef __nv_bfloat16 bf16;

// fp32 scratch
__device__ float g_xp [Tn*Bn*Dn];
__device__ float g_H  [Tn*Bn*Dn];
__device__ float g_P  [Tn*Bn*Dn];
__device__ float g_C  [Tn*Bn*Dn];
__device__ float g_CTX[Tn*Bn*Dn];
__device__ float g_Wt [Dn*Dn];

// split-bf16 scratch
__device__ bf16 g_Hb_hi [Tn*Bn*Dn];
__device__ bf16 g_Hb_lo [Tn*Bn*Dn];
__device__ bf16 g_Xb_hi [Tn*Bn*Dn];
__device__ bf16 g_Xb_lo [Tn*Bn*Dn];
__device__ bf16 g_WaT_hi[Dn*Dn];
__device__ bf16 g_WaT_lo[Dn*Dn];
__device__ bf16 g_UaT_hi[Dn*Dn];
__device__ bf16 g_UaT_lo[Dn*Dn];
__device__ bf16 g_fcWT_hi[Vn*2*Dn];
__device__ bf16 g_fcWT_lo[Vn*2*Dn];

// ---------------- scalar FFMA2 helpers (k_embed) -------------------------
#define FMA2(acc, a, w) \
    asm("fma.rn.f32x2 %0, %1, %2, %0;" : "+l"(acc) : "l"(a), "l"(w))
#define DUP2(dst, s) \
    asm("mov.b64 %0, {%1, %1};" : "=l"(dst) : "r"(s))

__device__ __forceinline__ unsigned smem_u32(const void* p) {
    return (unsigned)__cvta_generic_to_shared(p);
}

// ---------------- mma.sync helpers (baseline PTX, sm_80+) ----------------
#define LDSM_X4(r0_, r1_, r2_, r3_, addr) \
    asm volatile("ldmatrix.sync.aligned.m8n8.x4.shared.b16 {%0,%1,%2,%3}, [%4];" \
        : "=r"(r0_), "=r"(r1_), "=r"(r2_), "=r"(r3_) : "r"(addr))

#define MMA16816(d, a, b) \
    asm volatile("mma.sync.aligned.m16n8k16.row.col.f32.bf16.bf16.f32 " \
        "{%0,%1,%2,%3}, {%4,%5,%6,%7}, {%8,%9}, {%0,%1,%2,%3};" \
        : "+f"((d)[0]), "+f"((d)[1]), "+f"((d)[2]), "+f"((d)[3]) \
        : "r"((a)[0]), "r"((a)[1]), "r"((a)[2]), "r"((a)[3]), \
          "r"((b)[0]), "r"((b)[1]))

// ---------------------------------------------------------------------------
// 0) transpose W_hh
__global__ void k_transpose(const float* __restrict__ W) {
    int k = blockIdx.x, d = threadIdx.x;
    g_Wt[d*Dn + k] = W[k*Dn + d];
}

// split helpers / conversion kernels
__device__ __forceinline__ void split_bf16(float x, bf16& h, bf16& l) {
    h = __float2bfloat16(x);
    l = __float2bfloat16(x - __bfloat162float(h));
}
__global__ void k_cvtH() {
    int i = blockIdx.x*256 + threadIdx.x;
    split_bf16(g_H[i], g_Hb_hi[i], g_Hb_lo[i]);
}
__global__ void k_cvtX() {
    int i = blockIdx.x*256 + threadIdx.x;
    split_bf16(g_CTX[i], g_Xb_hi[i], g_Xb_lo[i]);
}
// convert + transpose weight [K][N] -> [N][K] hi/lo.  which: 0=Wa,1=Ua,2=fcW
__global__ void k_cvtWT(const float* __restrict__ W, int N, int K, int which) {
    int idx = blockIdx.x*256 + threadIdx.x;
    if (idx >= N*K) return;
    int n = idx / K, k = idx % K;
    bf16 h, l;
    split_bf16(W[k*N + n], h, l);
    if (which == 0)      { g_WaT_hi [idx] = h; g_WaT_lo [idx] = l; }
    else if (which == 1) { g_UaT_hi [idx] = h; g_UaT_lo [idx] = l; }
    else                 { g_fcWT_hi[idx] = h; g_fcWT_lo[idx] = l; }
}

// ===========================================================================
// scalar 128x128 FFMA2 core (k_embed only)
// ===========================================================================
__device__ __forceinline__ void gemm_core32(
    const float* As, const float* Ws, u64 accp[8][4], int ty8, int tx8)
{
#pragma unroll 8
    for (int kk = 0; kk < 32; kk++) {
        float4 a0 = *(const float4*)&As[kk*132 + ty8];
        float4 a1 = *(const float4*)&As[kk*132 + ty8 + 4];
        ulonglong2 w01 = *(const ulonglong2*)&Ws[kk*132 + tx8];
        ulonglong2 w23 = *(const ulonglong2*)&Ws[kk*132 + tx8 + 4];
        u64 wp0 = w01.x, wp1 = w01.y, wp2 = w23.x, wp3 = w23.y;
        u64 ad[8];
        DUP2(ad[0], __float_as_uint(a0.x));
        DUP2(ad[1], __float_as_uint(a0.y));
        DUP2(ad[2], __float_as_uint(a0.z));
        DUP2(ad[3], __float_as_uint(a0.w));
        DUP2(ad[4], __float_as_uint(a1.x));
        DUP2(ad[5], __float_as_uint(a1.y));
        DUP2(ad[6], __float_as_uint(a1.z));
        DUP2(ad[7], __float_as_uint(a1.w));
#pragma unroll
        for (int ii = 0; ii < 8; ii++) {
            FMA2(accp[ii][0], ad[ii], wp0);
            FMA2(accp[ii][1], ad[ii], wp1);
            FMA2(accp[ii][2], ad[ii], wp2);
            FMA2(accp[ii][3], ad[ii], wp3);
        }
    }
}

// ---------------------------------------------------------------------------
// 1) xp = embed[x] @ W_ih + b_h  (scalar FFMA2, proven)
__global__ void __launch_bounds__(256, 2) k_embed(
    const int* __restrict__ x, const float* __restrict__ embed,
    const float* __restrict__ Wih, const float* __restrict__ bh)
{
    __shared__ float As[32*132];
    __shared__ float Ws[32*132];
    __shared__ int   toks[128];
    int r0 = blockIdx.x * 128;
    int d0 = blockIdx.y * 128;
    int tid = threadIdx.x;
    int tx8 = (tid & 15) * 8, ty8 = (tid >> 4) * 8;

    if (tid < 128) {
        int r = r0 + tid, t = r >> 6, b = r & 63;
        toks[tid] = x[b*Tn + t];
    }

    u64 accp[8][4];
    {
        ulonglong2 b01 = *(const ulonglong2*)&bh[d0 + tx8];
        ulonglong2 b23 = *(const ulonglong2*)&bh[d0 + tx8 + 4];
#pragma unroll
        for (int ii = 0; ii < 8; ii++) {
            accp[ii][0] = b01.x; accp[ii][1] = b01.y;
            accp[ii][2] = b23.x; accp[ii][3] = b23.y;
        }
    }
    __syncthreads();

    for (int k0 = 0; k0 < En; k0 += 32) {
#pragma unroll
        for (int s = 0; s < 16; s++) {
            int idx = tid + s*256;
            int kk = idx & 31, i = idx >> 5;
            As[kk*132 + i] = embed[toks[i]*En + k0 + kk];
            int dd = idx & 127, kw = idx >> 7;
            Ws[kw*132 + dd] = Wih[(k0+kw)*Dn + d0 + dd];
        }
        __syncthreads();
        gemm_core32(As, Ws, accp, ty8, tx8);
        __syncthreads();
    }
#pragma unroll
    for (int ii = 0; ii < 8; ii++) {
        float* row = &g_xp[(r0 + ty8 + ii)*Dn + d0 + tx8];
        ((ulonglong2*)row)[0] = make_ulonglong2(accp[ii][0], accp[ii][1]);
        ((ulonglong2*)row)[1] = make_ulonglong2(accp[ii][2], accp[ii][3]);
    }
}

// ---------------------------------------------------------------------------
// 2) Recurrence (R9 version: split chains + double-buffered h)
__global__ void __launch_bounds__(256, 1) k_rnn() {
    extern __shared__ float sm[];
    float*  hbuf = sm;
    float4* Ws   = (float4*)(sm + 512);
    int b = blockIdx.x, d = threadIdx.x;

    const float* wtrow = &g_Wt[d*Dn];
    float4 wreg[32];
#pragma unroll
    for (int i = 0; i < 32; i++) wreg[i] = *(const float4*)(wtrow + 4*i);
#pragma unroll
    for (int i = 0; i < 32; i++) Ws[i*256 + d] = *(const float4*)(wtrow + 128 + 4*i);
    hbuf[d] = 0.f; hbuf[256 + d] = 0.f;
    __syncthreads();

    for (int t = 0; t < Tn; t++) {
        const float* hp = hbuf + (t & 1) * 256;
        float*       hc = hbuf + ((t & 1) ^ 1) * 256;
        float a0 = g_xp[(t*Bn + b)*Dn + d], a1 = 0.f, a2 = 0.f, a3 = 0.f;
        float b0 = 0.f, b1 = 0.f, b2 = 0.f, b3 = 0.f;
#pragma unroll
        for (int i = 0; i < 32; i += 4) {
            float4 h0 = *(const float4*)&hp[4*i];
            a0 = fmaf(wreg[i].x, h0.x, a0); a0 = fmaf(wreg[i].y, h0.y, a0);
            a0 = fmaf(wreg[i].z, h0.z, a0); a0 = fmaf(wreg[i].w, h0.w, a0);
            float4 h1 = *(const float4*)&hp[4*(i+1)];
            a1 = fmaf(wreg[i+1].x, h1.x, a1); a1 = fmaf(wreg[i+1].y, h1.y, a1);
            a1 = fmaf(wreg[i+1].z, h1.z, a1); a1 = fmaf(wreg[i+1].w, h1.w, a1);
            float4 h2 = *(const float4*)&hp[4*(i+2)];
            a2 = fmaf(wreg[i+2].x, h2.x, a2); a2 = fmaf(wreg[i+2].y, h2.y, a2);
            a2 = fmaf(wreg[i+2].z, h2.z, a2); a2 = fmaf(wreg[i+2].w, h2.w, a2);
            float4 h3 = *(const float4*)&hp[4*(i+3)];
            a3 = fmaf(wreg[i+3].x, h3.x, a3); a3 = fmaf(wreg[i+3].y, h3.y, a3);
            a3 = fmaf(wreg[i+3].z, h3.z, a3); a3 = fmaf(wreg[i+3].w, h3.w, a3);
        }
#pragma unroll
        for (int i = 0; i < 32; i += 4) {
            float4 w0 = Ws[i*256 + d];
            float4 h0 = *(const float4*)&hp[128 + 4*i];
            b0 = fmaf(w0.x, h0.x, b0); b0 = fmaf(w0.y, h0.y, b0);
            b0 = fmaf(w0.z, h0.z, b0); b0 = fmaf(w0.w, h0.w, b0);
            float4 w1 = Ws[(i+1)*256 + d];
            float4 h1 = *(const float4*)&hp[128 + 4*(i+1)];
            b1 = fmaf(w1.x, h1.x, b1); b1 = fmaf(w1.y, h1.y, b1);
            b1 = fmaf(w1.z, h1.z, b1); b1 = fmaf(w1.w, h1.w, b1);
            float4 w2 = Ws[(i+2)*256 + d];
            float4 h2 = *(const float4*)&hp[128 + 4*(i+2)];
            b2 = fmaf(w2.x, h2.x, b2); b2 = fmaf(w2.y, h2.y, b2);
            b2 = fmaf(w2.z, h2.z, b2); b2 = fmaf(w2.w, h2.w, b2);
            float4 w3 = Ws[(i+3)*256 + d];
            float4 h3 = *(const float4*)&hp[128 + 4*(i+3)];
            b3 = fmaf(w3.x, h3.x, b3); b3 = fmaf(w3.y, h3.y, b3);
            b3 = fmaf(w3.z, h3.z, b3); b3 = fmaf(w3.w, h3.w, b3);
        }
        float hv = tanhf(((a0 + a1) + (a2 + a3)) + ((b0 + b1) + (b2 + b3)));
        hc[d] = hv;
        g_H[(t*Bn + b)*Dn + d] = hv;
        __syncthreads();
    }
}

// ===========================================================================
// mma.sync split-bf16 GEMM: CTA 128(M)x128(N), 8 warps each 64x32.
// K staged in 32-chunks; smem rows padded to 80 B (conflict-free ldmatrix).
// 3 passes: hi*hi + hi*lo + lo*hi.
// ===========================================================================
constexpr int MMA_PITCH = 80;                // bytes per smem row (64 data + 16 pad)
constexpr int MMA_BUF   = 128 * MMA_PITCH;   // 10240 B per tile
// smem: [A_hi][A_lo][B_hi][B_lo] = 40960 B (static)

struct MMAArgs {
    const bf16 *Ahi0, *Alo0;
    const bf16 *Ahi1, *Alo1;
    int ksplit;
    int Ka;
    const bf16 *Bhi, *Blo;     // [N][K] row-major
    int Kb;
    int Ktot;
};

__device__ __forceinline__ void mma_gemm_body(
    char* smem, const MMAArgs& g, int r0, int n0, float d[4][4][4])
{
    int tid = threadIdx.x;
    int lane = tid & 31;
    int wid = tid >> 5;
    int wm = (wid & 1) * 64;        // warp M offset in tile
    int wn = (wid >> 1) * 32;       // warp N offset in tile

    char* sAh = smem;
    char* sAl = smem + MMA_BUF;
    char* sBh = smem + 2*MMA_BUF;
    char* sBl = smem + 3*MMA_BUF;

    // ldmatrix lane addressing (within tile)
    int a_row = lane & 15;                      // rows 0-15 of frag
    int a_koff = (lane >> 4) * 16;              // 0 / 16 B  (k 0-7 / 8-15)
    int b_nl  = (lane & 7) + ((lane >> 4) << 3);  // n row 0-7 / 8-15
    int b_koff = ((lane >> 3) & 1) * 16;

    unsigned uAh = smem_u32(sAh), uAl = smem_u32(sAl);
    unsigned uBh = smem_u32(sBh), uBl = smem_u32(sBl);

    int nchunks = g.Ktot / 32;
    for (int c = 0; c < nchunks; c++) {
        int kglob = c * 32;
        const bf16* Ah; const bf16* Al; int ka;
        if (kglob < g.ksplit) { Ah = g.Ahi0; Al = g.Alo0; ka = kglob; }
        else                  { Ah = g.Ahi1; Al = g.Alo1; ka = kglob - g.ksplit; }
        const bf16* srcAh = Ah + (long)r0*g.Ka + ka;
        const bf16* srcAl = Al + (long)r0*g.Ka + ka;
        const bf16* srcBh = g.Bhi + (long)n0*g.Kb + kglob;
        const bf16* srcBl = g.Blo + (long)n0*g.Kb + kglob;

        __syncthreads();
#pragma unroll
        for (int s = 0; s < 2; s++) {
            int idx = tid + s*256;
            int row = idx >> 2, c4 = idx & 3;
            *(uint4*)(sAh + row*MMA_PITCH + c4*16) = *(const uint4*)(srcAh + row*g.Ka + c4*8);
            *(uint4*)(sAl + row*MMA_PITCH + c4*16) = *(const uint4*)(srcAl + row*g.Ka + c4*8);
            *(uint4*)(sBh + row*MMA_PITCH + c4*16) = *(const uint4*)(srcBh + row*g.Kb + c4*8);
            *(uint4*)(sBl + row*MMA_PITCH + c4*16) = *(const uint4*)(srcBl + row*g.Kb + c4*8);
        }
        __syncthreads();

#pragma unroll
        for (int ks = 0; ks < 2; ks++) {
            int kb = ks * 32;   // byte offset of this k16 step
            unsigned Ahf[4][4], Alf[4][4], Bhf[4][2], Blf[4][2];
#pragma unroll
            for (int f = 0; f < 4; f++) {
                unsigned ra = (unsigned)((wm + f*16 + a_row)*MMA_PITCH + a_koff + kb);
                LDSM_X4(Ahf[f][0], Ahf[f][1], Ahf[f][2], Ahf[f][3], uAh + ra);
                LDSM_X4(Alf[f][0], Alf[f][1], Alf[f][2], Alf[f][3], uAl + ra);
            }
#pragma unroll
            for (int p = 0; p < 2; p++) {
                unsigned rb = (unsigned)((wn + p*16 + b_nl)*MMA_PITCH + b_koff + kb);
                LDSM_X4(Bhf[2*p][0], Bhf[2*p][1], Bhf[2*p+1][0], Bhf[2*p+1][1], uBh + rb);
                LDSM_X4(Blf[2*p][0], Blf[2*p][1], Blf[2*p+1][0], Blf[2*p+1][1], uBl + rb);
            }
#pragma unroll
            for (int f = 0; f < 4; f++) {
#pragma unroll
                for (int nf = 0; nf < 4; nf++) {
                    MMA16816(d[f][nf], Ahf[f], Bhf[nf]);
                    MMA16816(d[f][nf], Ahf[f], Blf[nf]);
                    MMA16816(d[f][nf], Alf[f], Bhf[nf]);
                }
            }
        }
    }
}

// ---------------------------------------------------------------------------
// 3) P = H @ W_attn (z=0), C = H @ U_attn (z=1)  — mma.sync
__global__ void __launch_bounds__(256, 1) k_proj_mma()
{
    __shared__ char smem[4*MMA_BUF];
    int r0 = blockIdx.x * 128;
    int n0 = blockIdx.y * 128;

    MMAArgs g;
    g.Ahi0 = g_Hb_hi; g.Alo0 = g_Hb_lo; g.Ahi1 = g_Hb_hi; g.Alo1 = g_Hb_lo;
    g.ksplit = 1 << 30; g.Ka = Dn;
    g.Bhi = blockIdx.z ? g_UaT_hi : g_WaT_hi;
    g.Blo = blockIdx.z ? g_UaT_lo : g_WaT_lo;
    g.Kb = Dn; g.Ktot = Dn;
    float* Out = blockIdx.z ? g_C : g_P;

    float d[4][4][4];
#pragma unroll
    for (int f = 0; f < 4; f++)
#pragma unroll
        for (int nf = 0; nf < 4; nf++)
#pragma unroll
            for (int e = 0; e < 4; e++) d[f][nf][e] = 0.f;

    mma_gemm_body(smem, g, r0, n0, d);

    int tid = threadIdx.x, lane = tid & 31, wid = tid >> 5;
    int wm = (wid & 1) * 64, wn = (wid >> 1) * 32;
#pragma unroll
    for (int f = 0; f < 4; f++) {
        int row = r0 + wm + f*16 + (lane >> 2);
#pragma unroll
        for (int nf = 0; nf < 4; nf++) {
            int col = n0 + wn + nf*8 + (lane & 3)*2;
            *(float2*)&Out[(long)row*Dn + col]     = make_float2(d[f][nf][0], d[f][nf][1]);
            *(float2*)&Out[(long)(row+8)*Dn + col] = make_float2(d[f][nf][2], d[f][nf][3]);
        }
    }
}

// ---------------------------------------------------------------------------
// 5) logits = [H | CTX] @ fc_W + fc_b  — mma.sync
__global__ void __launch_bounds__(256, 1) k_logits_mma(
    const float* __restrict__ fcb, float* __restrict__ out)
{
    __shared__ char smem[4*MMA_BUF];
    int r0 = blockIdx.x * 128;
    int n0 = blockIdx.y * 128;

    MMAArgs g;
    g.Ahi0 = g_Hb_hi; g.Alo0 = g_Hb_lo;
    g.Ahi1 = g_Xb_hi; g.Alo1 = g_Xb_lo;
    g.ksplit = Dn; g.Ka = Dn;
    g.Bhi = g_fcWT_hi; g.Blo = g_fcWT_lo;
    g.Kb = 2*Dn; g.Ktot = 2*Dn;

    float d[4][4][4];
#pragma unroll
    for (int f = 0; f < 4; f++)
#pragma unroll
        for (int nf = 0; nf < 4; nf++)
#pragma unroll
            for (int e = 0; e < 4; e++) d[f][nf][e] = 0.f;

    mma_gemm_body(smem, g, r0, n0, d);

    int tid = threadIdx.x, lane = tid & 31, wid = tid >> 5;
    int wm = (wid & 1) * 64, wn = (wid >> 1) * 32;
#pragma unroll
    for (int f = 0; f < 4; f++) {
        int r1 = r0 + wm + f*16 + (lane >> 2);
        int r2 = r1 + 8;
        int t1 = r1 >> 6, b1 = r1 & 63;
        int t2 = r2 >> 6, b2 = r2 & 63;
        float* o1 = &out[((long)b1*Tn + t1)*Vn];
        float* o2 = &out[((long)b2*Tn + t2)*Vn];
#pragma unroll
        for (int nf = 0; nf < 4; nf++) {
            int col = n0 + wn + nf*8 + (lane & 3)*2;
            float2 bv = *(const float2*)&fcb[col];
            *(float2*)&o1[col] = make_float2(d[f][nf][0] + bv.x, d[f][nf][1] + bv.y);
            *(float2*)&o2[col] = make_float2(d[f][nf][2] + bv.x, d[f][nf][3] + bv.y);
        }
    }
}

// ---------------------------------------------------------------------------
// 4) Bahdanau attention (unchanged — MUFU floor)
__global__ void __launch_bounds__(256) k_attn(const float* __restrict__ vat) {
    __shared__ float Cs[TT][Dn - 4];
    __shared__ float Cs2[TT][4];
    __shared__ float EsT[Tn][TT];
    int b  = blockIdx.y;
    int t0 = blockIdx.x * TT;
    int tid = threadIdx.x;
    int warp = tid >> 5, lane = tid & 31;

    for (int idx = tid; idx < TT*Dn; idx += 256) {
        int q = idx / Dn, d2 = idx % Dn;
        float v = g_C[((t0+q)*Bn + b)*Dn + d2];
        if (d2 < Dn - 4) Cs[q][d2] = v; else Cs2[q][d2 - (Dn-4)] = v;
    }
    float vreg[8];
#pragma unroll
    for (int j = 0; j < 8; j++) vreg[j] = vat[lane + 32*j];
    __syncthreads();

    int t_hi = t0 + TT;
    for (int tp = warp; tp < t_hi; tp += 8) {
        float p[8];
#pragma unroll
        for (int j = 0; j < 8; j++) p[j] = g_P[(tp*Bn + b)*Dn + lane + 32*j];
#pragma unroll
        for (int q = 0; q < TT; q++) {
            float s = 0.f;
#pragma unroll
            for (int j = 0; j < 8; j++) {
                int d2 = lane + 32*j;
                float cv = (d2 < Dn - 4) ? Cs[q][d2] : Cs2[q][d2 - (Dn-4)];
                float z = p[j] + cv;
                float th; asm("tanh.approx.f32 %0, %1;" : "=f"(th) : "f"(z));
                s = fmaf(vreg[j], th, s);
            }
#pragma unroll
            for (int o = 16; o; o >>= 1) s += __shfl_xor_sync(0xffffffffu, s, o);
            if (lane == 0) EsT[tp][q] = s;
        }
    }
    __syncthreads();

    for (int q = warp; q < TT; q += 8) {
        int tg = t0 + q;
        float mx = -3.4e38f;
        for (int tp = lane; tp < tg; tp += 32) mx = fmaxf(mx, EsT[tp][q]);
#pragma unroll
        for (int o = 16; o; o >>= 1) mx = fmaxf(mx, __shfl_xor_sync(0xffffffffu, mx, o));
        float sum = 0.f;
        for (int tp = lane; tp < tg; tp += 32) {
            float e = __expf(EsT[tp][q] - mx);
            EsT[tp][q] = e; sum += e;
        }
#pragma unroll
        for (int o = 16; o; o >>= 1) sum += __shfl_xor_sync(0xffffffffu, sum, o);
        float inv = tg > 0 ? 1.f / sum : 0.f;
        for (int tp = lane; tp < t_hi; tp += 32) {
            float wv = (tp < tg) ? EsT[tp][q] * inv : 0.f;
            EsT[tp][q] = wv;
        }
    }
    __syncthreads();

    int d = tid;
    float acc[TT];
#pragma unroll
    for (int q = 0; q < TT; q++) acc[q] = 0.f;
    int tmax = t0 + TT - 1;
    for (int tp = 0; tp < tmax; tp++) {
        float hval = g_H[(tp*Bn + b)*Dn + d];
#pragma unroll
        for (int q = 0; q < TT; q += 4) {
            float4 w = *(const float4*)&EsT[tp][q];
            acc[q]   = fmaf(w.x, hval, acc[q]);
            acc[q+1] = fmaf(w.y, hval, acc[q+1]);
            acc[q+2] = fmaf(w.z, hval, acc[q+2]);
            acc[q+3] = fmaf(w.w, hval, acc[q+3]);
        }
    }
#pragma unroll
    for (int q = 0; q < TT; q++) {
        int tg = t0 + q;
        float c = acc[q];
        if (tg == 0) c = g_H[b*Dn + d];
        g_CTX[(tg*Bn + b)*Dn + d] = c;
    }
}

// ---------------------------------------------------------------------------
extern "C" void kernel_launch(void* const* d_in, const int* in_sizes, int n_in,
                              void* d_out, int out_size)
{
    const int*   x     = (const int*)  d_in[0];
    const float* embed = (const float*)d_in[1];
    const float* Wih   = (const float*)d_in[2];
    const float* Whh   = (const float*)d_in[3];
    const float* bh    = (const float*)d_in[4];
    const float* Wat   = (const float*)d_in[5];
    const float* Uat   = (const float*)d_in[6];
    const float* vat   = (const float*)d_in[7];
    const float* fcW   = (const float*)d_in[8];
    const float* fcb   = (const float*)d_in[9];
    float* out = (float*)d_out;

    cudaFuncSetAttribute(k_rnn, cudaFuncAttributeMaxDynamicSharedMemorySize, 512*4 + 32*256*16);

    k_transpose<<<Dn, Dn>>>(Whh);
    k_cvtWT<<<(Dn*Dn)/256, 256>>>(Wat, Dn, Dn, 0);
    k_cvtWT<<<(Dn*Dn)/256, 256>>>(Uat, Dn, Dn, 1);
    k_cvtWT<<<(Vn*2*Dn + 255)/256, 256>>>(fcW, Vn, 2*Dn, 2);
    k_embed<<<dim3((Tn*Bn)/128, Dn/128), 256>>>(x, embed, Wih, bh);
    k_rnn<<<Bn, 256, 512*4 + 32*256*16>>>();
    k_cvtH<<<(Tn*Bn*Dn)/256, 256>>>();
    k_proj_mma<<<dim3((Tn*Bn)/128, Dn/128, 2), 256>>>();
    k_attn<<<dim3(Tn/TT, Bn), 256>>>(vat);
    k_cvtX<<<(Tn*Bn*Dn)/256, 256>>>();
    k_logits_mma<<<dim3((Tn*Bn)/128, Vn/128), 256>>>(fcb, out);
}

// round 14
// speedup vs baseline: 1.4882x; 1.0493x over previous
#include <cuda_runtime.h>
#include <cuda_bf16.h>
#include <cstdint>
#include <math.h>

// Problem dims: B=64, T=512, V=512, E=128, D=256
constexpr int Tn = 512, Bn = 64, Vn = 512, En = 128, Dn = 256;
constexpr int TT = 16;

typedef unsigned long long u64;
typedef __nv_bfloat16 bf16;

// fp32 scratch
__device__ float g_xp [Tn*Bn*Dn];
__device__ float g_H  [Tn*Bn*Dn];
__device__ float g_P  [Tn*Bn*Dn];
__device__ float g_C  [Tn*Bn*Dn];
__device__ float g_Wt [Dn*Dn];

// split-bf16 scratch
__device__ bf16 g_Hb_hi [Tn*Bn*Dn];
__device__ bf16 g_Hb_lo [Tn*Bn*Dn];
__device__ bf16 g_Xb_hi [Tn*Bn*Dn];
__device__ bf16 g_Xb_lo [Tn*Bn*Dn];
__device__ bf16 g_WaT_hi[Dn*Dn];
__device__ bf16 g_WaT_lo[Dn*Dn];
__device__ bf16 g_UaT_hi[Dn*Dn];
__device__ bf16 g_UaT_lo[Dn*Dn];
__device__ bf16 g_fcWT_hi[Vn*2*Dn];
__device__ bf16 g_fcWT_lo[Vn*2*Dn];
__device__ bf16 g_WihT_hi[Dn*En];
__device__ bf16 g_WihT_lo[Dn*En];
__device__ bf16 g_Eb_hi [Vn*En];
__device__ bf16 g_Eb_lo [Vn*En];

// packed f32x2 fma
#define FMA2(acc, a, w) \
    asm("fma.rn.f32x2 %0, %1, %2, %0;" : "+l"(acc) : "l"(a), "l"(w))

__device__ __forceinline__ unsigned smem_u32(const void* p) {
    return (unsigned)__cvta_generic_to_shared(p);
}
__device__ __forceinline__ float hadd2(u64 v) {
    unsigned lo, hi;
    asm("mov.b64 {%0,%1}, %2;" : "=r"(lo), "=r"(hi) : "l"(v));
    return __uint_as_float(lo) + __uint_as_float(hi);
}

// ---------------- mma.sync helpers (baseline PTX, sm_80+) ----------------
#define LDSM_X4(r0_, r1_, r2_, r3_, addr) \
    asm volatile("ldmatrix.sync.aligned.m8n8.x4.shared.b16 {%0,%1,%2,%3}, [%4];" \
        : "=r"(r0_), "=r"(r1_), "=r"(r2_), "=r"(r3_) : "r"(addr))

#define MMA16816(d, a, b) \
    asm volatile("mma.sync.aligned.m16n8k16.row.col.f32.bf16.bf16.f32 " \
        "{%0,%1,%2,%3}, {%4,%5,%6,%7}, {%8,%9}, {%0,%1,%2,%3};" \
        : "+f"((d)[0]), "+f"((d)[1]), "+f"((d)[2]), "+f"((d)[3]) \
        : "r"((a)[0]), "r"((a)[1]), "r"((a)[2]), "r"((a)[3]), \
          "r"((b)[0]), "r"((b)[1]))

// ---------------------------------------------------------------------------
// 0) transpose W_hh
__global__ void k_transpose(const float* __restrict__ W) {
    int k = blockIdx.x, d = threadIdx.x;
    g_Wt[d*Dn + k] = W[k*Dn + d];
}

// split helpers / conversion kernels
__device__ __forceinline__ void split_bf16(float x, bf16& h, bf16& l) {
    h = __float2bfloat16(x);
    l = __float2bfloat16(x - __bfloat162float(h));
}
// convert + transpose weight [K][N] -> [N][K] hi/lo.
// which: 0=Wa, 1=Ua, 2=fcW, 3=Wih
__global__ void k_cvtWT(const float* __restrict__ W, int N, int K, int which) {
    int idx = blockIdx.x*256 + threadIdx.x;
    if (idx >= N*K) return;
    int n = idx / K, k = idx % K;
    bf16 h, l;
    split_bf16(W[k*N + n], h, l);
    if (which == 0)      { g_WaT_hi [idx] = h; g_WaT_lo [idx] = l; }
    else if (which == 1) { g_UaT_hi [idx] = h; g_UaT_lo [idx] = l; }
    else if (which == 2) { g_fcWT_hi[idx] = h; g_fcWT_lo[idx] = l; }
    else                 { g_WihT_hi[idx] = h; g_WihT_lo[idx] = l; }
}
__global__ void k_cvtE(const float* __restrict__ E) {
    int i = blockIdx.x*256 + threadIdx.x;
    split_bf16(E[i], g_Eb_hi[i], g_Eb_lo[i]);
}

// ---------------------------------------------------------------------------
// 2) Recurrence: h_t = tanh(xp_t + h_{t-1} @ W_hh), one CTA per batch row.
//    FFMA2-packed accumulation (k-pairs) + double-buffered h, 1 barrier/step.
//    Epilogue also writes split-bf16 H (feeds mma GEMMs).
__global__ void __launch_bounds__(256, 1) k_rnn() {
    extern __shared__ float sm[];
    float*      hbuf = sm;                          // 2 x 256
    ulonglong2* Ws   = (ulonglong2*)(sm + 512);     // [32][256] = 128 KB
    int b = blockIdx.x, d = threadIdx.x;

    const float* wtrow = &g_Wt[d*Dn];
    ulonglong2 wreg[32];
#pragma unroll
    for (int i = 0; i < 32; i++) wreg[i] = *(const ulonglong2*)(wtrow + 4*i);
#pragma unroll
    for (int i = 0; i < 32; i++) Ws[i*256 + d] = *(const ulonglong2*)(wtrow + 128 + 4*i);
    hbuf[d] = 0.f; hbuf[256 + d] = 0.f;
    __syncthreads();

    for (int t = 0; t < Tn; t++) {
        const float* hp = hbuf + (t & 1) * 256;
        float*       hc = hbuf + ((t & 1) ^ 1) * 256;
        float xpv = g_xp[(t*Bn + b)*Dn + d];
        u64 c0 = (u64)__float_as_uint(xpv);   // (xp, 0)
        u64 c1 = 0, c2 = 0, c3 = 0, c4 = 0, c5 = 0, c6 = 0, c7 = 0;
#pragma unroll
        for (int i = 0; i < 32; i += 2) {
            ulonglong2 h0 = *(const ulonglong2*)&hp[4*i];
            FMA2(c0, h0.x, wreg[i].x);   FMA2(c1, h0.y, wreg[i].y);
            ulonglong2 h1 = *(const ulonglong2*)&hp[4*(i+1)];
            FMA2(c2, h1.x, wreg[i+1].x); FMA2(c3, h1.y, wreg[i+1].y);
        }
#pragma unroll
        for (int i = 0; i < 32; i += 2) {
            ulonglong2 w0 = Ws[i*256 + d];
            ulonglong2 h0 = *(const ulonglong2*)&hp[128 + 4*i];
            FMA2(c4, h0.x, w0.x); FMA2(c5, h0.y, w0.y);
            ulonglong2 w1 = Ws[(i+1)*256 + d];
            ulonglong2 h1 = *(const ulonglong2*)&hp[128 + 4*(i+1)];
            FMA2(c6, h1.x, w1.x); FMA2(c7, h1.y, w1.y);
        }
        float hv = tanhf(((hadd2(c0) + hadd2(c1)) + (hadd2(c2) + hadd2(c3)))
                       + ((hadd2(c4) + hadd2(c5)) + (hadd2(c6) + hadd2(c7))));
        hc[d] = hv;
        int gi = (t*Bn + b)*Dn + d;
        g_H[gi] = hv;
        bf16 hh, hl; split_bf16(hv, hh, hl);
        g_Hb_hi[gi] = hh; g_Hb_lo[gi] = hl;
        __syncthreads();
    }
}

// ===========================================================================
// mma.sync split-bf16 GEMM: CTA 128(M)x128(N), 8 warps each 64x32.
// K staged in 32-chunks; smem rows padded to 80 B (conflict-free ldmatrix).
// 3 passes: hi*hi + hi*lo + lo*hi.  Optional A-row gather via ridx.
// ===========================================================================
constexpr int MMA_PITCH = 80;
constexpr int MMA_BUF   = 128 * MMA_PITCH;   // 10240 B per tile

struct MMAArgs {
    const bf16 *Ahi0, *Alo0;
    const bf16 *Ahi1, *Alo1;
    int ksplit;
    int Ka;
    const bf16 *Bhi, *Blo;     // [N][K] row-major
    int Kb;
    int Ktot;
};

__device__ __forceinline__ void mma_gemm_body(
    char* smem, const MMAArgs& g, int r0, int n0, float d[4][4][4],
    const int* __restrict__ ridx)
{
    int tid = threadIdx.x;
    int lane = tid & 31;
    int wid = tid >> 5;
    int wm = (wid & 1) * 64;
    int wn = (wid >> 1) * 32;

    char* sAh = smem;
    char* sAl = smem + MMA_BUF;
    char* sBh = smem + 2*MMA_BUF;
    char* sBl = smem + 3*MMA_BUF;

    int a_row = lane & 15;
    int a_koff = (lane >> 4) * 16;
    int b_nl  = (lane & 7) + ((lane >> 4) << 3);
    int b_koff = ((lane >> 3) & 1) * 16;

    unsigned uAh = smem_u32(sAh), uAl = smem_u32(sAl);
    unsigned uBh = smem_u32(sBh), uBl = smem_u32(sBl);

    int nchunks = g.Ktot / 32;
    for (int c = 0; c < nchunks; c++) {
        int kglob = c * 32;
        const bf16* Ah; const bf16* Al; int ka;
        if (kglob < g.ksplit) { Ah = g.Ahi0; Al = g.Alo0; ka = kglob; }
        else                  { Ah = g.Ahi1; Al = g.Alo1; ka = kglob - g.ksplit; }
        const bf16* srcBh = g.Bhi + (long)n0*g.Kb + kglob;
        const bf16* srcBl = g.Blo + (long)n0*g.Kb + kglob;

        __syncthreads();
#pragma unroll
        for (int s = 0; s < 2; s++) {
            int idx = tid + s*256;
            int row = idx >> 2, c4 = idx & 3;
            long arow = ridx ? (long)ridx[row] : (long)(r0 + row);
            *(uint4*)(sAh + row*MMA_PITCH + c4*16) = *(const uint4*)(Ah + arow*g.Ka + ka + c4*8);
            *(uint4*)(sAl + row*MMA_PITCH + c4*16) = *(const uint4*)(Al + arow*g.Ka + ka + c4*8);
            *(uint4*)(sBh + row*MMA_PITCH + c4*16) = *(const uint4*)(srcBh + row*g.Kb + c4*8);
            *(uint4*)(sBl + row*MMA_PITCH + c4*16) = *(const uint4*)(srcBl + row*g.Kb + c4*8);
        }
        __syncthreads();

#pragma unroll
        for (int ks = 0; ks < 2; ks++) {
            int kb = ks * 32;
            unsigned Ahf[4][4], Alf[4][4], Bhf[4][2], Blf[4][2];
#pragma unroll
            for (int f = 0; f < 4; f++) {
                unsigned ra = (unsigned)((wm + f*16 + a_row)*MMA_PITCH + a_koff + kb);
                LDSM_X4(Ahf[f][0], Ahf[f][1], Ahf[f][2], Ahf[f][3], uAh + ra);
                LDSM_X4(Alf[f][0], Alf[f][1], Alf[f][2], Alf[f][3], uAl + ra);
            }
#pragma unroll
            for (int p = 0; p < 2; p++) {
                unsigned rb = (unsigned)((wn + p*16 + b_nl)*MMA_PITCH + b_koff + kb);
                LDSM_X4(Bhf[2*p][0], Bhf[2*p][1], Bhf[2*p+1][0], Bhf[2*p+1][1], uBh + rb);
                LDSM_X4(Blf[2*p][0], Blf[2*p][1], Blf[2*p+1][0], Blf[2*p+1][1], uBl + rb);
            }
#pragma unroll
            for (int f = 0; f < 4; f++) {
#pragma unroll
                for (int nf = 0; nf < 4; nf++) {
                    MMA16816(d[f][nf], Ahf[f], Bhf[nf]);
                    MMA16816(d[f][nf], Ahf[f], Blf[nf]);
                    MMA16816(d[f][nf], Alf[f], Bhf[nf]);
                }
            }
        }
    }
}

#define ZERO_ACC(d) \
    _Pragma("unroll") for (int f_ = 0; f_ < 4; f_++) \
    _Pragma("unroll") for (int n_ = 0; n_ < 4; n_++) \
    _Pragma("unroll") for (int e_ = 0; e_ < 4; e_++) (d)[f_][n_][e_] = 0.f;

// ---------------------------------------------------------------------------
// 1) xp = embed[x] @ W_ih + b_h  — mma.sync with token gather
__global__ void __launch_bounds__(256, 1) k_embed_mma(
    const int* __restrict__ x, const float* __restrict__ bh)
{
    __shared__ char smem[4*MMA_BUF];
    __shared__ int  toks[128];
    int r0 = blockIdx.x * 128;
    int n0 = blockIdx.y * 128;
    int tid = threadIdx.x;

    if (tid < 128) {
        int r = r0 + tid, t = r >> 6, b = r & 63;
        toks[tid] = x[b*Tn + t];
    }
    __syncthreads();

    MMAArgs g;
    g.Ahi0 = g_Eb_hi; g.Alo0 = g_Eb_lo; g.Ahi1 = g_Eb_hi; g.Alo1 = g_Eb_lo;
    g.ksplit = 1 << 30; g.Ka = En;
    g.Bhi = g_WihT_hi; g.Blo = g_WihT_lo;
    g.Kb = En; g.Ktot = En;

    float d[4][4][4];
    ZERO_ACC(d)
    mma_gemm_body(smem, g, r0, n0, d, toks);

    int lane = tid & 31, wid = tid >> 5;
    int wm = (wid & 1) * 64, wn = (wid >> 1) * 32;
#pragma unroll
    for (int f = 0; f < 4; f++) {
        int row = r0 + wm + f*16 + (lane >> 2);
#pragma unroll
        for (int nf = 0; nf < 4; nf++) {
            int col = n0 + wn + nf*8 + (lane & 3)*2;
            float2 bv = *(const float2*)&bh[col];
            *(float2*)&g_xp[(long)row*Dn + col]     = make_float2(d[f][nf][0]+bv.x, d[f][nf][1]+bv.y);
            *(float2*)&g_xp[(long)(row+8)*Dn + col] = make_float2(d[f][nf][2]+bv.x, d[f][nf][3]+bv.y);
        }
    }
}

// ---------------------------------------------------------------------------
// 3) P = H @ W_attn (z=0), C = H @ U_attn (z=1)  — mma.sync
__global__ void __launch_bounds__(256, 1) k_proj_mma()
{
    __shared__ char smem[4*MMA_BUF];
    int r0 = blockIdx.x * 128;
    int n0 = blockIdx.y * 128;

    MMAArgs g;
    g.Ahi0 = g_Hb_hi; g.Alo0 = g_Hb_lo; g.Ahi1 = g_Hb_hi; g.Alo1 = g_Hb_lo;
    g.ksplit = 1 << 30; g.Ka = Dn;
    g.Bhi = blockIdx.z ? g_UaT_hi : g_WaT_hi;
    g.Blo = blockIdx.z ? g_UaT_lo : g_WaT_lo;
    g.Kb = Dn; g.Ktot = Dn;
    float* Out = blockIdx.z ? g_C : g_P;

    float d[4][4][4];
    ZERO_ACC(d)
    mma_gemm_body(smem, g, r0, n0, d, nullptr);

    int tid = threadIdx.x, lane = tid & 31, wid = tid >> 5;
    int wm = (wid & 1) * 64, wn = (wid >> 1) * 32;
#pragma unroll
    for (int f = 0; f < 4; f++) {
        int row = r0 + wm + f*16 + (lane >> 2);
#pragma unroll
        for (int nf = 0; nf < 4; nf++) {
            int col = n0 + wn + nf*8 + (lane & 3)*2;
            *(float2*)&Out[(long)row*Dn + col]     = make_float2(d[f][nf][0], d[f][nf][1]);
            *(float2*)&Out[(long)(row+8)*Dn + col] = make_float2(d[f][nf][2], d[f][nf][3]);
        }
    }
}

// ---------------------------------------------------------------------------
// 5) logits = [H | CTX] @ fc_W + fc_b  — mma.sync
__global__ void __launch_bounds__(256, 1) k_logits_mma(
    const float* __restrict__ fcb, float* __restrict__ out)
{
    __shared__ char smem[4*MMA_BUF];
    int r0 = blockIdx.x * 128;
    int n0 = blockIdx.y * 128;

    MMAArgs g;
    g.Ahi0 = g_Hb_hi; g.Alo0 = g_Hb_lo;
    g.Ahi1 = g_Xb_hi; g.Alo1 = g_Xb_lo;
    g.ksplit = Dn; g.Ka = Dn;
    g.Bhi = g_fcWT_hi; g.Blo = g_fcWT_lo;
    g.Kb = 2*Dn; g.Ktot = 2*Dn;

    float d[4][4][4];
    ZERO_ACC(d)
    mma_gemm_body(smem, g, r0, n0, d, nullptr);

    int tid = threadIdx.x, lane = tid & 31, wid = tid >> 5;
    int wm = (wid & 1) * 64, wn = (wid >> 1) * 32;
#pragma unroll
    for (int f = 0; f < 4; f++) {
        int r1 = r0 + wm + f*16 + (lane >> 2);
        int r2 = r1 + 8;
        int t1 = r1 >> 6, b1 = r1 & 63;
        int t2 = r2 >> 6, b2 = r2 & 63;
        float* o1 = &out[((long)b1*Tn + t1)*Vn];
        float* o2 = &out[((long)b2*Tn + t2)*Vn];
#pragma unroll
        for (int nf = 0; nf < 4; nf++) {
            int col = n0 + wn + nf*8 + (lane & 3)*2;
            float2 bv = *(const float2*)&fcb[col];
            *(float2*)&o1[col] = make_float2(d[f][nf][0] + bv.x, d[f][nf][1] + bv.y);
            *(float2*)&o2[col] = make_float2(d[f][nf][2] + bv.x, d[f][nf][3] + bv.y);
        }
    }
}

// ---------------------------------------------------------------------------
// 4) Bahdanau attention (MUFU floor); pass-3 writes split-bf16 ctx directly.
__global__ void __launch_bounds__(256) k_attn(const float* __restrict__ vat) {
    __shared__ float Cs[TT][Dn - 4];
    __shared__ float Cs2[TT][4];
    __shared__ float EsT[Tn][TT];
    int b  = blockIdx.y;
    int t0 = blockIdx.x * TT;
    int tid = threadIdx.x;
    int warp = tid >> 5, lane = tid & 31;

    for (int idx = tid; idx < TT*Dn; idx += 256) {
        int q = idx / Dn, d2 = idx % Dn;
        float v = g_C[((t0+q)*Bn + b)*Dn + d2];
        if (d2 < Dn - 4) Cs[q][d2] = v; else Cs2[q][d2 - (Dn-4)] = v;
    }
    float vreg[8];
#pragma unroll
    for (int j = 0; j < 8; j++) vreg[j] = vat[lane + 32*j];
    __syncthreads();

    int t_hi = t0 + TT;
    for (int tp = warp; tp < t_hi; tp += 8) {
        float p[8];
#pragma unroll
        for (int j = 0; j < 8; j++) p[j] = g_P[(tp*Bn + b)*Dn + lane + 32*j];
#pragma unroll
        for (int q = 0; q < TT; q++) {
            float s = 0.f;
#pragma unroll
            for (int j = 0; j < 8; j++) {
                int d2 = lane + 32*j;
                float cv = (d2 < Dn - 4) ? Cs[q][d2] : Cs2[q][d2 - (Dn-4)];
                float z = p[j] + cv;
                float th; asm("tanh.approx.f32 %0, %1;" : "=f"(th) : "f"(z));
                s = fmaf(vreg[j], th, s);
            }
#pragma unroll
            for (int o = 16; o; o >>= 1) s += __shfl_xor_sync(0xffffffffu, s, o);
            if (lane == 0) EsT[tp][q] = s;
        }
    }
    __syncthreads();

    for (int q = warp; q < TT; q += 8) {
        int tg = t0 + q;
        float mx = -3.4e38f;
        for (int tp = lane; tp < tg; tp += 32) mx = fmaxf(mx, EsT[tp][q]);
#pragma unroll
        for (int o = 16; o; o >>= 1) mx = fmaxf(mx, __shfl_xor_sync(0xffffffffu, mx, o));
        float sum = 0.f;
        for (int tp = lane; tp < tg; tp += 32) {
            float e = __expf(EsT[tp][q] - mx);
            EsT[tp][q] = e; sum += e;
        }
#pragma unroll
        for (int o = 16; o; o >>= 1) sum += __shfl_xor_sync(0xffffffffu, sum, o);
        float inv = tg > 0 ? 1.f / sum : 0.f;
        for (int tp = lane; tp < t_hi; tp += 32) {
            float wv = (tp < tg) ? EsT[tp][q] * inv : 0.f;
            EsT[tp][q] = wv;
        }
    }
    __syncthreads();

    int d = tid;
    float acc[TT];
#pragma unroll
    for (int q = 0; q < TT; q++) acc[q] = 0.f;
    int tmax = t0 + TT - 1;
    for (int tp = 0; tp < tmax; tp++) {
        float hval = g_H[(tp*Bn + b)*Dn + d];
#pragma unroll
        for (int q = 0; q < TT; q += 4) {
            float4 w = *(const float4*)&EsT[tp][q];
            acc[q]   = fmaf(w.x, hval, acc[q]);
            acc[q+1] = fmaf(w.y, hval, acc[q+1]);
            acc[q+2] = fmaf(w.z, hval, acc[q+2]);
            acc[q+3] = fmaf(w.w, hval, acc[q+3]);
        }
    }
#pragma unroll
    for (int q = 0; q < TT; q++) {
        int tg = t0 + q;
        float c = acc[q];
        if (tg == 0) c = g_H[b*Dn + d];
        int gi = (tg*Bn + b)*Dn + d;
        bf16 hh, hl; split_bf16(c, hh, hl);
        g_Xb_hi[gi] = hh; g_Xb_lo[gi] = hl;
    }
}

// ---------------------------------------------------------------------------
extern "C" void kernel_launch(void* const* d_in, const int* in_sizes, int n_in,
                              void* d_out, int out_size)
{
    const int*   x     = (const int*)  d_in[0];
    const float* embed = (const float*)d_in[1];
    const float* Wih   = (const float*)d_in[2];
    const float* Whh   = (const float*)d_in[3];
    const float* bh    = (const float*)d_in[4];
    const float* Wat   = (const float*)d_in[5];
    const float* Uat   = (const float*)d_in[6];
    const float* vat   = (const float*)d_in[7];
    const float* fcW   = (const float*)d_in[8];
    const float* fcb   = (const float*)d_in[9];
    float* out = (float*)d_out;

    cudaFuncSetAttribute(k_rnn, cudaFuncAttributeMaxDynamicSharedMemorySize, 512*4 + 32*256*16);

    k_transpose<<<Dn, Dn>>>(Whh);
    k_cvtWT<<<(Dn*Dn)/256, 256>>>(Wat, Dn, Dn, 0);
    k_cvtWT<<<(Dn*Dn)/256, 256>>>(Uat, Dn, Dn, 1);
    k_cvtWT<<<(Vn*2*Dn)/256, 256>>>(fcW, Vn, 2*Dn, 2);
    k_cvtWT<<<(Dn*En)/256, 256>>>(Wih, Dn, En, 3);
    k_cvtE<<<(Vn*En)/256, 256>>>(embed);
    k_embed_mma<<<dim3((Tn*Bn)/128, Dn/128), 256>>>(x, bh);
    k_rnn<<<Bn, 256, 512*4 + 32*256*16>>>();
    k_proj_mma<<<dim3((Tn*Bn)/128, Dn/128, 2), 256>>>();
    k_attn<<<dim3(Tn/TT, Bn), 256>>>(vat);
    k_logits_mma<<<dim3((Tn*Bn)/128, Vn/128), 256>>>(fcb, out);
}

// round 15
// speedup vs baseline: 1.6537x; 1.1112x over previous
#include <cuda_runtime.h>
#include <cuda_bf16.h>
#include <cstdint>
#include <math.h>

// Problem dims: B=64, T=512, V=512, E=128, D=256
constexpr int Tn = 512, Bn = 64, Vn = 512, En = 128, Dn = 256;
constexpr int TT = 16;

typedef unsigned long long u64;
typedef __nv_bfloat16 bf16;

// fp32 scratch
__device__ float g_xp [Tn*Bn*Dn];
__device__ float g_H  [Tn*Bn*Dn];
__device__ float g_P  [Tn*Bn*Dn];
__device__ float g_C  [Tn*Bn*Dn];
__device__ float g_Wt [Dn*Dn];

// split-bf16 scratch
__device__ bf16 g_Hb_hi [Tn*Bn*Dn];
__device__ bf16 g_Hb_lo [Tn*Bn*Dn];
__device__ bf16 g_Xb_hi [Tn*Bn*Dn];
__device__ bf16 g_Xb_lo [Tn*Bn*Dn];
__device__ bf16 g_WaT_hi[Dn*Dn];
__device__ bf16 g_WaT_lo[Dn*Dn];
__device__ bf16 g_UaT_hi[Dn*Dn];
__device__ bf16 g_UaT_lo[Dn*Dn];
__device__ bf16 g_fcWT_hi[Vn*2*Dn];
__device__ bf16 g_fcWT_lo[Vn*2*Dn];
__device__ bf16 g_WihT_hi[Dn*En];
__device__ bf16 g_WihT_lo[Dn*En];
__device__ bf16 g_Eb_hi [Vn*En];
__device__ bf16 g_Eb_lo [Vn*En];

// packed f32x2 fma
#define FMA2(acc, a, w) \
    asm("fma.rn.f32x2 %0, %1, %2, %0;" : "+l"(acc) : "l"(a), "l"(w))

__device__ __forceinline__ unsigned smem_u32(const void* p) {
    return (unsigned)__cvta_generic_to_shared(p);
}
__device__ __forceinline__ float hadd2(u64 v) {
    unsigned lo, hi;
    asm("mov.b64 {%0,%1}, %2;" : "=r"(lo), "=r"(hi) : "l"(v));
    return __uint_as_float(lo) + __uint_as_float(hi);
}

// ---------------- mma.sync helpers (baseline PTX, sm_80+) ----------------
#define LDSM_X4(r0_, r1_, r2_, r3_, addr) \
    asm volatile("ldmatrix.sync.aligned.m8n8.x4.shared.b16 {%0,%1,%2,%3}, [%4];" \
        : "=r"(r0_), "=r"(r1_), "=r"(r2_), "=r"(r3_) : "r"(addr))

#define MMA16816(d, a, b) \
    asm volatile("mma.sync.aligned.m16n8k16.row.col.f32.bf16.bf16.f32 " \
        "{%0,%1,%2,%3}, {%4,%5,%6,%7}, {%8,%9}, {%0,%1,%2,%3};" \
        : "+f"((d)[0]), "+f"((d)[1]), "+f"((d)[2]), "+f"((d)[3]) \
        : "r"((a)[0]), "r"((a)[1]), "r"((a)[2]), "r"((a)[3]), \
          "r"((b)[0]), "r"((b)[1]))

// ---------------------------------------------------------------------------
// 0) transpose W_hh
__global__ void k_transpose(const float* __restrict__ W) {
    int k = blockIdx.x, d = threadIdx.x;
    g_Wt[d*Dn + k] = W[k*Dn + d];
}

// split helpers / conversion kernels
__device__ __forceinline__ void split_bf16(float x, bf16& h, bf16& l) {
    h = __float2bfloat16(x);
    l = __float2bfloat16(x - __bfloat162float(h));
}
// convert + transpose weight [K][N] -> [N][K] hi/lo.
// which: 0=Wa, 1=Ua, 2=fcW, 3=Wih
__global__ void k_cvtWT(const float* __restrict__ W, int N, int K, int which) {
    int idx = blockIdx.x*256 + threadIdx.x;
    if (idx >= N*K) return;
    int n = idx / K, k = idx % K;
    bf16 h, l;
    split_bf16(W[k*N + n], h, l);
    if (which == 0)      { g_WaT_hi [idx] = h; g_WaT_lo [idx] = l; }
    else if (which == 1) { g_UaT_hi [idx] = h; g_UaT_lo [idx] = l; }
    else if (which == 2) { g_fcWT_hi[idx] = h; g_fcWT_lo[idx] = l; }
    else                 { g_WihT_hi[idx] = h; g_WihT_lo[idx] = l; }
}
__global__ void k_cvtE(const float* __restrict__ E) {
    int i = blockIdx.x*256 + threadIdx.x;
    split_bf16(E[i], g_Eb_hi[i], g_Eb_lo[i]);
}

// ---------------------------------------------------------------------------
// 2) Recurrence: h_t = tanh(xp_t + h_{t-1} @ W_hh), one CTA per batch row.
//    W split 192 in regs / 64 in smem (crossbar wavefronts halved vs 128/128).
//    FFMA2 accumulation, double-buffered h, 1 barrier/step.
__global__ void __launch_bounds__(256, 1) k_rnn() {
    extern __shared__ float sm[];
    float*      hbuf = sm;                          // 2 x 256
    ulonglong2* Ws   = (ulonglong2*)(sm + 512);     // [16][256] = 64 KB
    int b = blockIdx.x, d = threadIdx.x;

    const float* wtrow = &g_Wt[d*Dn];
    ulonglong2 wreg[48];                            // k 0..191 (192 regs)
#pragma unroll
    for (int i = 0; i < 48; i++) wreg[i] = *(const ulonglong2*)(wtrow + 4*i);
#pragma unroll
    for (int i = 0; i < 16; i++) Ws[i*256 + d] = *(const ulonglong2*)(wtrow + 192 + 4*i);
    hbuf[d] = 0.f; hbuf[256 + d] = 0.f;
    __syncthreads();

    for (int t = 0; t < Tn; t++) {
        const float* hp = hbuf + (t & 1) * 256;
        float*       hc = hbuf + ((t & 1) ^ 1) * 256;
        float xpv = g_xp[(t*Bn + b)*Dn + d];
        u64 c0 = (u64)__float_as_uint(xpv);   // (xp, 0)
        u64 c1 = 0, c2 = 0, c3 = 0, c4 = 0, c5 = 0, c6 = 0, c7 = 0;
#pragma unroll
        for (int i = 0; i < 48; i += 2) {
            ulonglong2 h0 = *(const ulonglong2*)&hp[4*i];
            FMA2(c0, h0.x, wreg[i].x);   FMA2(c1, h0.y, wreg[i].y);
            ulonglong2 h1 = *(const ulonglong2*)&hp[4*(i+1)];
            FMA2(c2, h1.x, wreg[i+1].x); FMA2(c3, h1.y, wreg[i+1].y);
        }
#pragma unroll
        for (int i = 0; i < 16; i += 2) {
            ulonglong2 w0 = Ws[i*256 + d];
            ulonglong2 h0 = *(const ulonglong2*)&hp[192 + 4*i];
            FMA2(c4, h0.x, w0.x); FMA2(c5, h0.y, w0.y);
            ulonglong2 w1 = Ws[(i+1)*256 + d];
            ulonglong2 h1 = *(const ulonglong2*)&hp[192 + 4*(i+1)];
            FMA2(c6, h1.x, w1.x); FMA2(c7, h1.y, w1.y);
        }
        float hv = tanhf(((hadd2(c0) + hadd2(c1)) + (hadd2(c2) + hadd2(c3)))
                       + ((hadd2(c4) + hadd2(c5)) + (hadd2(c6) + hadd2(c7))));
        hc[d] = hv;
        int gi = (t*Bn + b)*Dn + d;
        g_H[gi] = hv;
        bf16 hh, hl; split_bf16(hv, hh, hl);
        g_Hb_hi[gi] = hh; g_Hb_lo[gi] = hl;
        __syncthreads();
    }
}

// ===========================================================================
// mma.sync split-bf16 GEMM: CTA 128(M)x128(N), 8 warps each 64x32.
// Double-buffered 32-k chunks (stage c+1 overlaps mma on c; 1 barrier/chunk).
// 3 passes: hi*hi + hi*lo + lo*hi.  Optional A-row gather via ridx.
// ===========================================================================
constexpr int MMA_PITCH = 80;
constexpr int MMA_BUF   = 128 * MMA_PITCH;   // 10240 B per tile
constexpr int MMA_SMEM  = 8 * MMA_BUF;       // 2 buffers x 4 tiles = 81920 B

struct MMAArgs {
    const bf16 *Ahi0, *Alo0;
    const bf16 *Ahi1, *Alo1;
    int ksplit;
    int Ka;
    const bf16 *Bhi, *Blo;     // [N][K] row-major
    int Kb;
    int Ktot;
};

__device__ __forceinline__ void stage_chunk(
    char* base, const MMAArgs& g, int r0, int n0, int c,
    const int* __restrict__ ridx, int tid)
{
    int kglob = c * 32;
    const bf16* Ah; const bf16* Al; int ka;
    if (kglob < g.ksplit) { Ah = g.Ahi0; Al = g.Alo0; ka = kglob; }
    else                  { Ah = g.Ahi1; Al = g.Alo1; ka = kglob - g.ksplit; }
    const bf16* srcBh = g.Bhi + (long)n0*g.Kb + kglob;
    const bf16* srcBl = g.Blo + (long)n0*g.Kb + kglob;
    char* sAh = base;
    char* sAl = base + MMA_BUF;
    char* sBh = base + 2*MMA_BUF;
    char* sBl = base + 3*MMA_BUF;
#pragma unroll
    for (int s = 0; s < 2; s++) {
        int idx = tid + s*256;
        int row = idx >> 2, c4 = idx & 3;
        long arow = ridx ? (long)ridx[row] : (long)(r0 + row);
        *(uint4*)(sAh + row*MMA_PITCH + c4*16) = *(const uint4*)(Ah + arow*g.Ka + ka + c4*8);
        *(uint4*)(sAl + row*MMA_PITCH + c4*16) = *(const uint4*)(Al + arow*g.Ka + ka + c4*8);
        *(uint4*)(sBh + row*MMA_PITCH + c4*16) = *(const uint4*)(srcBh + row*g.Kb + c4*8);
        *(uint4*)(sBl + row*MMA_PITCH + c4*16) = *(const uint4*)(srcBl + row*g.Kb + c4*8);
    }
}

__device__ __forceinline__ void mma_gemm_body(
    char* smem, const MMAArgs& g, int r0, int n0, float d[4][4][4],
    const int* __restrict__ ridx)
{
    int tid = threadIdx.x;
    int lane = tid & 31;
    int wid = tid >> 5;
    int wm = (wid & 1) * 64;
    int wn = (wid >> 1) * 32;

    int a_row = lane & 15;
    int a_koff = (lane >> 4) * 16;
    int b_nl  = (lane & 7) + ((lane >> 4) << 3);
    int b_koff = ((lane >> 3) & 1) * 16;

    int nchunks = g.Ktot / 32;
    stage_chunk(smem, g, r0, n0, 0, ridx, tid);
    __syncthreads();

    for (int c = 0; c < nchunks; c++) {
        char* cur = smem + (c & 1) * (4*MMA_BUF);
        if (c + 1 < nchunks)
            stage_chunk(smem + ((c+1) & 1) * (4*MMA_BUF), g, r0, n0, c+1, ridx, tid);

        unsigned uAh = smem_u32(cur);
        unsigned uAl = uAh + MMA_BUF;
        unsigned uBh = uAh + 2*MMA_BUF;
        unsigned uBl = uAh + 3*MMA_BUF;

#pragma unroll
        for (int ks = 0; ks < 2; ks++) {
            int kb = ks * 32;
            unsigned Bhf[4][2], Blf[4][2];
#pragma unroll
            for (int p = 0; p < 2; p++) {
                unsigned rb = (unsigned)((wn + p*16 + b_nl)*MMA_PITCH + b_koff + kb);
                LDSM_X4(Bhf[2*p][0], Bhf[2*p][1], Bhf[2*p+1][0], Bhf[2*p+1][1], uBh + rb);
                LDSM_X4(Blf[2*p][0], Blf[2*p][1], Blf[2*p+1][0], Blf[2*p+1][1], uBl + rb);
            }
#pragma unroll
            for (int f = 0; f < 4; f++) {
                unsigned Ahf[4], Alf[4];
                unsigned ra = (unsigned)((wm + f*16 + a_row)*MMA_PITCH + a_koff + kb);
                LDSM_X4(Ahf[0], Ahf[1], Ahf[2], Ahf[3], uAh + ra);
                LDSM_X4(Alf[0], Alf[1], Alf[2], Alf[3], uAl + ra);
#pragma unroll
                for (int nf = 0; nf < 4; nf++) {
                    MMA16816(d[f][nf], Ahf, Bhf[nf]);
                    MMA16816(d[f][nf], Ahf, Blf[nf]);
                    MMA16816(d[f][nf], Alf, Bhf[nf]);
                }
            }
        }
        __syncthreads();
    }
}

#define ZERO_ACC(d) \
    _Pragma("unroll") for (int f_ = 0; f_ < 4; f_++) \
    _Pragma("unroll") for (int n_ = 0; n_ < 4; n_++) \
    _Pragma("unroll") for (int e_ = 0; e_ < 4; e_++) (d)[f_][n_][e_] = 0.f;

// ---------------------------------------------------------------------------
// 1) xp = embed[x] @ W_ih + b_h  — mma.sync with token gather
__global__ void __launch_bounds__(256) k_embed_mma(
    const int* __restrict__ x, const float* __restrict__ bh)
{
    extern __shared__ char smem[];
    __shared__ int toks[128];
    int r0 = blockIdx.x * 128;
    int n0 = blockIdx.y * 128;
    int tid = threadIdx.x;

    if (tid < 128) {
        int r = r0 + tid, t = r >> 6, b = r & 63;
        toks[tid] = x[b*Tn + t];
    }
    __syncthreads();

    MMAArgs g;
    g.Ahi0 = g_Eb_hi; g.Alo0 = g_Eb_lo; g.Ahi1 = g_Eb_hi; g.Alo1 = g_Eb_lo;
    g.ksplit = 1 << 30; g.Ka = En;
    g.Bhi = g_WihT_hi; g.Blo = g_WihT_lo;
    g.Kb = En; g.Ktot = En;

    float d[4][4][4];
    ZERO_ACC(d)
    mma_gemm_body(smem, g, r0, n0, d, toks);

    int lane = tid & 31, wid = tid >> 5;
    int wm = (wid & 1) * 64, wn = (wid >> 1) * 32;
#pragma unroll
    for (int f = 0; f < 4; f++) {
        int row = r0 + wm + f*16 + (lane >> 2);
#pragma unroll
        for (int nf = 0; nf < 4; nf++) {
            int col = n0 + wn + nf*8 + (lane & 3)*2;
            float2 bv = *(const float2*)&bh[col];
            *(float2*)&g_xp[(long)row*Dn + col]     = make_float2(d[f][nf][0]+bv.x, d[f][nf][1]+bv.y);
            *(float2*)&g_xp[(long)(row+8)*Dn + col] = make_float2(d[f][nf][2]+bv.x, d[f][nf][3]+bv.y);
        }
    }
}

// ---------------------------------------------------------------------------
// 3) P = H @ W_attn (z=0), C = H @ U_attn (z=1)  — mma.sync
__global__ void __launch_bounds__(256) k_proj_mma()
{
    extern __shared__ char smem[];
    int r0 = blockIdx.x * 128;
    int n0 = blockIdx.y * 128;

    MMAArgs g;
    g.Ahi0 = g_Hb_hi; g.Alo0 = g_Hb_lo; g.Ahi1 = g_Hb_hi; g.Alo1 = g_Hb_lo;
    g.ksplit = 1 << 30; g.Ka = Dn;
    g.Bhi = blockIdx.z ? g_UaT_hi : g_WaT_hi;
    g.Blo = blockIdx.z ? g_UaT_lo : g_WaT_lo;
    g.Kb = Dn; g.Ktot = Dn;
    float* Out = blockIdx.z ? g_C : g_P;

    float d[4][4][4];
    ZERO_ACC(d)
    mma_gemm_body(smem, g, r0, n0, d, nullptr);

    int tid = threadIdx.x, lane = tid & 31, wid = tid >> 5;
    int wm = (wid & 1) * 64, wn = (wid >> 1) * 32;
#pragma unroll
    for (int f = 0; f < 4; f++) {
        int row = r0 + wm + f*16 + (lane >> 2);
#pragma unroll
        for (int nf = 0; nf < 4; nf++) {
            int col = n0 + wn + nf*8 + (lane & 3)*2;
            *(float2*)&Out[(long)row*Dn + col]     = make_float2(d[f][nf][0], d[f][nf][1]);
            *(float2*)&Out[(long)(row+8)*Dn + col] = make_float2(d[f][nf][2], d[f][nf][3]);
        }
    }
}

// ---------------------------------------------------------------------------
// 5) logits = [H | CTX] @ fc_W + fc_b  — mma.sync
__global__ void __launch_bounds__(256) k_logits_mma(
    const float* __restrict__ fcb, float* __restrict__ out)
{
    extern __shared__ char smem[];
    int r0 = blockIdx.x * 128;
    int n0 = blockIdx.y * 128;

    MMAArgs g;
    g.Ahi0 = g_Hb_hi; g.Alo0 = g_Hb_lo;
    g.Ahi1 = g_Xb_hi; g.Alo1 = g_Xb_lo;
    g.ksplit = Dn; g.Ka = Dn;
    g.Bhi = g_fcWT_hi; g.Blo = g_fcWT_lo;
    g.Kb = 2*Dn; g.Ktot = 2*Dn;

    float d[4][4][4];
    ZERO_ACC(d)
    mma_gemm_body(smem, g, r0, n0, d, nullptr);

    int tid = threadIdx.x, lane = tid & 31, wid = tid >> 5;
    int wm = (wid & 1) * 64, wn = (wid >> 1) * 32;
#pragma unroll
    for (int f = 0; f < 4; f++) {
        int r1 = r0 + wm + f*16 + (lane >> 2);
        int r2 = r1 + 8;
        int t1 = r1 >> 6, b1 = r1 & 63;
        int t2 = r2 >> 6, b2 = r2 & 63;
        float* o1 = &out[((long)b1*Tn + t1)*Vn];
        float* o2 = &out[((long)b2*Tn + t2)*Vn];
#pragma unroll
        for (int nf = 0; nf < 4; nf++) {
            int col = n0 + wn + nf*8 + (lane & 3)*2;
            float2 bv = *(const float2*)&fcb[col];
            *(float2*)&o1[col] = make_float2(d[f][nf][0] + bv.x, d[f][nf][1] + bv.y);
            *(float2*)&o2[col] = make_float2(d[f][nf][2] + bv.x, d[f][nf][3] + bv.y);
        }
    }
}

// ---------------------------------------------------------------------------
// 4) Bahdanau attention (MUFU floor); pass-3 writes split-bf16 ctx directly.
__global__ void __launch_bounds__(256) k_attn(const float* __restrict__ vat) {
    __shared__ float Cs[TT][Dn - 4];
    __shared__ float Cs2[TT][4];
    __shared__ float EsT[Tn][TT];
    int b  = blockIdx.y;
    int t0 = blockIdx.x * TT;
    int tid = threadIdx.x;
    int warp = tid >> 5, lane = tid & 31;

    for (int idx = tid; idx < TT*Dn; idx += 256) {
        int q = idx / Dn, d2 = idx % Dn;
        float v = g_C[((t0+q)*Bn + b)*Dn + d2];
        if (d2 < Dn - 4) Cs[q][d2] = v; else Cs2[q][d2 - (Dn-4)] = v;
    }
    float vreg[8];
#pragma unroll
    for (int j = 0; j < 8; j++) vreg[j] = vat[lane + 32*j];
    __syncthreads();

    int t_hi = t0 + TT;
    for (int tp = warp; tp < t_hi; tp += 8) {
        float p[8];
#pragma unroll
        for (int j = 0; j < 8; j++) p[j] = g_P[(tp*Bn + b)*Dn + lane + 32*j];
#pragma unroll
        for (int q = 0; q < TT; q++) {
            float s = 0.f;
#pragma unroll
            for (int j = 0; j < 8; j++) {
                int d2 = lane + 32*j;
                float cv = (d2 < Dn - 4) ? Cs[q][d2] : Cs2[q][d2 - (Dn-4)];
                float z = p[j] + cv;
                float th; asm("tanh.approx.f32 %0, %1;" : "=f"(th) : "f"(z));
                s = fmaf(vreg[j], th, s);
            }
#pragma unroll
            for (int o = 16; o; o >>= 1) s += __shfl_xor_sync(0xffffffffu, s, o);
            if (lane == 0) EsT[tp][q] = s;
        }
    }
    __syncthreads();

    for (int q = warp; q < TT; q += 8) {
        int tg = t0 + q;
        float mx = -3.4e38f;
        for (int tp = lane; tp < tg; tp += 32) mx = fmaxf(mx, EsT[tp][q]);
#pragma unroll
        for (int o = 16; o; o >>= 1) mx = fmaxf(mx, __shfl_xor_sync(0xffffffffu, mx, o));
        float sum = 0.f;
        for (int tp = lane; tp < tg; tp += 32) {
            float e = __expf(EsT[tp][q] - mx);
            EsT[tp][q] = e; sum += e;
        }
#pragma unroll
        for (int o = 16; o; o >>= 1) sum += __shfl_xor_sync(0xffffffffu, sum, o);
        float inv = tg > 0 ? 1.f / sum : 0.f;
        for (int tp = lane; tp < t_hi; tp += 32) {
            float wv = (tp < tg) ? EsT[tp][q] * inv : 0.f;
            EsT[tp][q] = wv;
        }
    }
    __syncthreads();

    int d = tid;
    float acc[TT];
#pragma unroll
    for (int q = 0; q < TT; q++) acc[q] = 0.f;
    int tmax = t0 + TT - 1;
    for (int tp = 0; tp < tmax; tp++) {
        float hval = g_H[(tp*Bn + b)*Dn + d];
#pragma unroll
        for (int q = 0; q < TT; q += 4) {
            float4 w = *(const float4*)&EsT[tp][q];
            acc[q]   = fmaf(w.x, hval, acc[q]);
            acc[q+1] = fmaf(w.y, hval, acc[q+1]);
            acc[q+2] = fmaf(w.z, hval, acc[q+2]);
            acc[q+3] = fmaf(w.w, hval, acc[q+3]);
        }
    }
#pragma unroll
    for (int q = 0; q < TT; q++) {
        int tg = t0 + q;
        float c = acc[q];
        if (tg == 0) c = g_H[b*Dn + d];
        int gi = (tg*Bn + b)*Dn + d;
        bf16 hh, hl; split_bf16(c, hh, hl);
        g_Xb_hi[gi] = hh; g_Xb_lo[gi] = hl;
    }
}

// ---------------------------------------------------------------------------
extern "C" void kernel_launch(void* const* d_in, const int* in_sizes, int n_in,
                              void* d_out, int out_size)
{
    const int*   x     = (const int*)  d_in[0];
    const float* embed = (const float*)d_in[1];
    const float* Wih   = (const float*)d_in[2];
    const float* Whh   = (const float*)d_in[3];
    const float* bh    = (const float*)d_in[4];
    const float* Wat   = (const float*)d_in[5];
    const float* Uat   = (const float*)d_in[6];
    const float* vat   = (const float*)d_in[7];
    const float* fcW   = (const float*)d_in[8];
    const float* fcb   = (const float*)d_in[9];
    float* out = (float*)d_out;

    int rnn_smem = 512*4 + 16*256*16;   // 67584
    cudaFuncSetAttribute(k_rnn,        cudaFuncAttributeMaxDynamicSharedMemorySize, rnn_smem);
    cudaFuncSetAttribute(k_embed_mma,  cudaFuncAttributeMaxDynamicSharedMemorySize, MMA_SMEM);
    cudaFuncSetAttribute(k_proj_mma,   cudaFuncAttributeMaxDynamicSharedMemorySize, MMA_SMEM);
    cudaFuncSetAttribute(k_logits_mma, cudaFuncAttributeMaxDynamicSharedMemorySize, MMA_SMEM);

    k_transpose<<<Dn, Dn>>>(Whh);
    k_cvtWT<<<(Dn*Dn)/256, 256>>>(Wat, Dn, Dn, 0);
    k_cvtWT<<<(Dn*Dn)/256, 256>>>(Uat, Dn, Dn, 1);
    k_cvtWT<<<(Vn*2*Dn)/256, 256>>>(fcW, Vn, 2*Dn, 2);
    k_cvtWT<<<(Dn*En)/256, 256>>>(Wih, Dn, En, 3);
    k_cvtE<<<(Vn*En)/256, 256>>>(embed);
    k_embed_mma<<<dim3((Tn*Bn)/128, Dn/128), 256, MMA_SMEM>>>(x, bh);
    k_rnn<<<Bn, 256, rnn_smem>>>();
    k_proj_mma<<<dim3((Tn*Bn)/128, Dn/128, 2), 256, MMA_SMEM>>>();
    k_attn<<<dim3(Tn/TT, Bn), 256>>>(vat);
    k_logits_mma<<<dim3((Tn*Bn)/128, Vn/128), 256, MMA_SMEM>>>(fcb, out);
}

// round 16
// speedup vs baseline: 1.6712x; 1.0106x over previous
#include <cuda_runtime.h>
#include <cuda_bf16.h>
#include <cstdint>
#include <math.h>

// Problem dims: B=64, T=512, V=512, E=128, D=256
constexpr int Tn = 512, Bn = 64, Vn = 512, En = 128, Dn = 256;
constexpr int TT = 16;

typedef unsigned long long u64;
typedef __nv_bfloat16 bf16;

// fp32 scratch
__device__ float g_xp [Tn*Bn*Dn];
__device__ float g_H  [Tn*Bn*Dn];
__device__ float g_P  [Tn*Bn*Dn];
__device__ float g_C  [Tn*Bn*Dn];
__device__ float g_Wt [Dn*Dn];

// split-bf16 scratch
__device__ bf16 g_Hb_hi [Tn*Bn*Dn];
__device__ bf16 g_Hb_lo [Tn*Bn*Dn];
__device__ bf16 g_Xb_hi [Tn*Bn*Dn];
__device__ bf16 g_Xb_lo [Tn*Bn*Dn];
__device__ bf16 g_WaT_hi[Dn*Dn];
__device__ bf16 g_WaT_lo[Dn*Dn];
__device__ bf16 g_UaT_hi[Dn*Dn];
__device__ bf16 g_UaT_lo[Dn*Dn];
__device__ bf16 g_fcWT_hi[Vn*2*Dn];
__device__ bf16 g_fcWT_lo[Vn*2*Dn];
__device__ bf16 g_WihT_hi[Dn*En];
__device__ bf16 g_WihT_lo[Dn*En];
__device__ bf16 g_Eb_hi [Vn*En];
__device__ bf16 g_Eb_lo [Vn*En];

// packed f32x2 fma
#define FMA2(acc, a, w) \
    asm("fma.rn.f32x2 %0, %1, %2, %0;" : "+l"(acc) : "l"(a), "l"(w))

__device__ __forceinline__ unsigned smem_u32(const void* p) {
    return (unsigned)__cvta_generic_to_shared(p);
}
__device__ __forceinline__ float hadd2(u64 v) {
    unsigned lo, hi;
    asm("mov.b64 {%0,%1}, %2;" : "=r"(lo), "=r"(hi) : "l"(v));
    return __uint_as_float(lo) + __uint_as_float(hi);
}

// ---------------- mma.sync helpers (baseline PTX, sm_80+) ----------------
#define LDSM_X4(r0_, r1_, r2_, r3_, addr) \
    asm volatile("ldmatrix.sync.aligned.m8n8.x4.shared.b16 {%0,%1,%2,%3}, [%4];" \
        : "=r"(r0_), "=r"(r1_), "=r"(r2_), "=r"(r3_) : "r"(addr))

#define MMA16816(d, a, b) \
    asm volatile("mma.sync.aligned.m16n8k16.row.col.f32.bf16.bf16.f32 " \
        "{%0,%1,%2,%3}, {%4,%5,%6,%7}, {%8,%9}, {%0,%1,%2,%3};" \
        : "+f"((d)[0]), "+f"((d)[1]), "+f"((d)[2]), "+f"((d)[3]) \
        : "r"((a)[0]), "r"((a)[1]), "r"((a)[2]), "r"((a)[3]), \
          "r"((b)[0]), "r"((b)[1]))

// ---------------------------------------------------------------------------
// 0) transpose W_hh
__global__ void k_transpose(const float* __restrict__ W) {
    int k = blockIdx.x, d = threadIdx.x;
    g_Wt[d*Dn + k] = W[k*Dn + d];
}

__device__ __forceinline__ void split_bf16(float x, bf16& h, bf16& l) {
    h = __float2bfloat16(x);
    l = __float2bfloat16(x - __bfloat162float(h));
}

// ---------------------------------------------------------------------------
// 0b) ALL weight conversions in one kernel (region-decoded).
//     regions: [0,65536) WaT | [65536,131072) UaT | [131072,393216) fcWT
//              [393216,425984) WihT | [425984,491520) E (no transpose)
__global__ void __launch_bounds__(256) k_cvt_all(
    const float* __restrict__ Wa, const float* __restrict__ Ua,
    const float* __restrict__ fcW, const float* __restrict__ Wih,
    const float* __restrict__ E)
{
    int idx = blockIdx.x*256 + threadIdx.x;
    bf16 h, l;
    if (idx < 65536) {                       // WaT: N=256, K=256
        int n = idx >> 8, k = idx & 255;
        split_bf16(Wa[k*Dn + n], h, l);
        g_WaT_hi[idx] = h; g_WaT_lo[idx] = l;
    } else if (idx < 131072) {               // UaT
        int lcl = idx - 65536;
        int n = lcl >> 8, k = lcl & 255;
        split_bf16(Ua[k*Dn + n], h, l);
        g_UaT_hi[lcl] = h; g_UaT_lo[lcl] = l;
    } else if (idx < 393216) {               // fcWT: N=512, K=512
        int lcl = idx - 131072;
        int n = lcl >> 9, k = lcl & 511;
        split_bf16(fcW[k*Vn + n], h, l);
        g_fcWT_hi[lcl] = h; g_fcWT_lo[lcl] = l;
    } else if (idx < 425984) {               // WihT: N=256, K=128
        int lcl = idx - 393216;
        int n = lcl >> 7, k = lcl & 127;
        split_bf16(Wih[k*Dn + n], h, l);
        g_WihT_hi[lcl] = h; g_WihT_lo[lcl] = l;
    } else {                                 // embed: straight split
        int lcl = idx - 425984;
        split_bf16(E[lcl], h, l);
        g_Eb_hi[lcl] = h; g_Eb_lo[lcl] = l;
    }
}

// ---------------------------------------------------------------------------
// 2) Recurrence: h_t = tanh(xp_t + h_{t-1} @ W_hh), one CTA per batch row.
//    W split 208 in regs / 48 in smem. FFMA2 accumulation, double-buffered h.
__global__ void __launch_bounds__(256, 1) k_rnn() {
    extern __shared__ float sm[];
    float*      hbuf = sm;                          // 2 x 256
    ulonglong2* Ws   = (ulonglong2*)(sm + 512);     // [12][256] = 48 KB
    int b = blockIdx.x, d = threadIdx.x;

    const float* wtrow = &g_Wt[d*Dn];
    ulonglong2 wreg[52];                            // k 0..207 (208 regs)
#pragma unroll
    for (int i = 0; i < 52; i++) wreg[i] = *(const ulonglong2*)(wtrow + 4*i);
#pragma unroll
    for (int i = 0; i < 12; i++) Ws[i*256 + d] = *(const ulonglong2*)(wtrow + 208 + 4*i);
    hbuf[d] = 0.f; hbuf[256 + d] = 0.f;
    __syncthreads();

    for (int t = 0; t < Tn; t++) {
        const float* hp = hbuf + (t & 1) * 256;
        float*       hc = hbuf + ((t & 1) ^ 1) * 256;
        float xpv = g_xp[(t*Bn + b)*Dn + d];
        u64 c0 = (u64)__float_as_uint(xpv);   // (xp, 0)
        u64 c1 = 0, c2 = 0, c3 = 0, c4 = 0, c5 = 0, c6 = 0, c7 = 0;
#pragma unroll
        for (int i = 0; i < 52; i += 2) {
            ulonglong2 h0 = *(const ulonglong2*)&hp[4*i];
            FMA2(c0, h0.x, wreg[i].x);   FMA2(c1, h0.y, wreg[i].y);
            ulonglong2 h1 = *(const ulonglong2*)&hp[4*(i+1)];
            FMA2(c2, h1.x, wreg[i+1].x); FMA2(c3, h1.y, wreg[i+1].y);
        }
#pragma unroll
        for (int i = 0; i < 12; i += 2) {
            ulonglong2 w0 = Ws[i*256 + d];
            ulonglong2 h0 = *(const ulonglong2*)&hp[208 + 4*i];
            FMA2(c4, h0.x, w0.x); FMA2(c5, h0.y, w0.y);
            ulonglong2 w1 = Ws[(i+1)*256 + d];
            ulonglong2 h1 = *(const ulonglong2*)&hp[208 + 4*(i+1)];
            FMA2(c6, h1.x, w1.x); FMA2(c7, h1.y, w1.y);
        }
        float hv = tanhf(((hadd2(c0) + hadd2(c1)) + (hadd2(c2) + hadd2(c3)))
                       + ((hadd2(c4) + hadd2(c5)) + (hadd2(c6) + hadd2(c7))));
        hc[d] = hv;
        int gi = (t*Bn + b)*Dn + d;
        g_H[gi] = hv;
        bf16 hh, hl; split_bf16(hv, hh, hl);
        g_Hb_hi[gi] = hh; g_Hb_lo[gi] = hl;
        __syncthreads();
    }
}

// ===========================================================================
// mma.sync split-bf16 GEMM: CTA 128(M)x128(N), 8 warps each 64x32.
// Double-buffered 32-k chunks. 3 passes: hi*hi + hi*lo + lo*hi.
// ===========================================================================
constexpr int MMA_PITCH = 80;
constexpr int MMA_BUF   = 128 * MMA_PITCH;   // 10240 B per tile
constexpr int MMA_SMEM  = 8 * MMA_BUF;       // 2 buffers x 4 tiles = 81920 B

struct MMAArgs {
    const bf16 *Ahi0, *Alo0;
    const bf16 *Ahi1, *Alo1;
    int ksplit;
    int Ka;
    const bf16 *Bhi, *Blo;     // [N][K] row-major
    int Kb;
    int Ktot;
};

__device__ __forceinline__ void stage_chunk(
    char* base, const MMAArgs& g, int r0, int n0, int c,
    const int* __restrict__ ridx, int tid)
{
    int kglob = c * 32;
    const bf16* Ah; const bf16* Al; int ka;
    if (kglob < g.ksplit) { Ah = g.Ahi0; Al = g.Alo0; ka = kglob; }
    else                  { Ah = g.Ahi1; Al = g.Alo1; ka = kglob - g.ksplit; }
    const bf16* srcBh = g.Bhi + (long)n0*g.Kb + kglob;
    const bf16* srcBl = g.Blo + (long)n0*g.Kb + kglob;
    char* sAh = base;
    char* sAl = base + MMA_BUF;
    char* sBh = base + 2*MMA_BUF;
    char* sBl = base + 3*MMA_BUF;
#pragma unroll
    for (int s = 0; s < 2; s++) {
        int idx = tid + s*256;
        int row = idx >> 2, c4 = idx & 3;
        long arow = ridx ? (long)ridx[row] : (long)(r0 + row);
        *(uint4*)(sAh + row*MMA_PITCH + c4*16) = *(const uint4*)(Ah + arow*g.Ka + ka + c4*8);
        *(uint4*)(sAl + row*MMA_PITCH + c4*16) = *(const uint4*)(Al + arow*g.Ka + ka + c4*8);
        *(uint4*)(sBh + row*MMA_PITCH + c4*16) = *(const uint4*)(srcBh + row*g.Kb + c4*8);
        *(uint4*)(sBl + row*MMA_PITCH + c4*16) = *(const uint4*)(srcBl + row*g.Kb + c4*8);
    }
}

__device__ __forceinline__ void mma_gemm_body(
    char* smem, const MMAArgs& g, int r0, int n0, float d[4][4][4],
    const int* __restrict__ ridx)
{
    int tid = threadIdx.x;
    int lane = tid & 31;
    int wid = tid >> 5;
    int wm = (wid & 1) * 64;
    int wn = (wid >> 1) * 32;

    int a_row = lane & 15;
    int a_koff = (lane >> 4) * 16;
    int b_nl  = (lane & 7) + ((lane >> 4) << 3);
    int b_koff = ((lane >> 3) & 1) * 16;

    int nchunks = g.Ktot / 32;
    stage_chunk(smem, g, r0, n0, 0, ridx, tid);
    __syncthreads();

    for (int c = 0; c < nchunks; c++) {
        char* cur = smem + (c & 1) * (4*MMA_BUF);
        if (c + 1 < nchunks)
            stage_chunk(smem + ((c+1) & 1) * (4*MMA_BUF), g, r0, n0, c+1, ridx, tid);

        unsigned uAh = smem_u32(cur);
        unsigned uAl = uAh + MMA_BUF;
        unsigned uBh = uAh + 2*MMA_BUF;
        unsigned uBl = uAh + 3*MMA_BUF;

#pragma unroll
        for (int ks = 0; ks < 2; ks++) {
            int kb = ks * 32;
            unsigned Bhf[4][2], Blf[4][2];
#pragma unroll
            for (int p = 0; p < 2; p++) {
                unsigned rb = (unsigned)((wn + p*16 + b_nl)*MMA_PITCH + b_koff + kb);
                LDSM_X4(Bhf[2*p][0], Bhf[2*p][1], Bhf[2*p+1][0], Bhf[2*p+1][1], uBh + rb);
                LDSM_X4(Blf[2*p][0], Blf[2*p][1], Blf[2*p+1][0], Blf[2*p+1][1], uBl + rb);
            }
#pragma unroll
            for (int f = 0; f < 4; f++) {
                unsigned Ahf[4], Alf[4];
                unsigned ra = (unsigned)((wm + f*16 + a_row)*MMA_PITCH + a_koff + kb);
                LDSM_X4(Ahf[0], Ahf[1], Ahf[2], Ahf[3], uAh + ra);
                LDSM_X4(Alf[0], Alf[1], Alf[2], Alf[3], uAl + ra);
#pragma unroll
                for (int nf = 0; nf < 4; nf++) {
                    MMA16816(d[f][nf], Ahf, Bhf[nf]);
                    MMA16816(d[f][nf], Ahf, Blf[nf]);
                    MMA16816(d[f][nf], Alf, Bhf[nf]);
                }
            }
        }
        __syncthreads();
    }
}

#define ZERO_ACC(d) \
    _Pragma("unroll") for (int f_ = 0; f_ < 4; f_++) \
    _Pragma("unroll") for (int n_ = 0; n_ < 4; n_++) \
    _Pragma("unroll") for (int e_ = 0; e_ < 4; e_++) (d)[f_][n_][e_] = 0.f;

// ---------------------------------------------------------------------------
// 1) xp = embed[x] @ W_ih + b_h  — mma.sync with token gather
__global__ void __launch_bounds__(256) k_embed_mma(
    const int* __restrict__ x, const float* __restrict__ bh)
{
    extern __shared__ char smem[];
    __shared__ int toks[128];
    int r0 = blockIdx.x * 128;
    int n0 = blockIdx.y * 128;
    int tid = threadIdx.x;

    if (tid < 128) {
        int r = r0 + tid, t = r >> 6, b = r & 63;
        toks[tid] = x[b*Tn + t];
    }
    __syncthreads();

    MMAArgs g;
    g.Ahi0 = g_Eb_hi; g.Alo0 = g_Eb_lo; g.Ahi1 = g_Eb_hi; g.Alo1 = g_Eb_lo;
    g.ksplit = 1 << 30; g.Ka = En;
    g.Bhi = g_WihT_hi; g.Blo = g_WihT_lo;
    g.Kb = En; g.Ktot = En;

    float d[4][4][4];
    ZERO_ACC(d)
    mma_gemm_body(smem, g, r0, n0, d, toks);

    int lane = tid & 31, wid = tid >> 5;
    int wm = (wid & 1) * 64, wn = (wid >> 1) * 32;
#pragma unroll
    for (int f = 0; f < 4; f++) {
        int row = r0 + wm + f*16 + (lane >> 2);
#pragma unroll
        for (int nf = 0; nf < 4; nf++) {
            int col = n0 + wn + nf*8 + (lane & 3)*2;
            float2 bv = *(const float2*)&bh[col];
            *(float2*)&g_xp[(long)row*Dn + col]     = make_float2(d[f][nf][0]+bv.x, d[f][nf][1]+bv.y);
            *(float2*)&g_xp[(long)(row+8)*Dn + col] = make_float2(d[f][nf][2]+bv.x, d[f][nf][3]+bv.y);
        }
    }
}

// ---------------------------------------------------------------------------
// 3) P = H @ W_attn (z=0), C = H @ U_attn (z=1)  — mma.sync
__global__ void __launch_bounds__(256) k_proj_mma()
{
    extern __shared__ char smem[];
    int r0 = blockIdx.x * 128;
    int n0 = blockIdx.y * 128;

    MMAArgs g;
    g.Ahi0 = g_Hb_hi; g.Alo0 = g_Hb_lo; g.Ahi1 = g_Hb_hi; g.Alo1 = g_Hb_lo;
    g.ksplit = 1 << 30; g.Ka = Dn;
    g.Bhi = blockIdx.z ? g_UaT_hi : g_WaT_hi;
    g.Blo = blockIdx.z ? g_UaT_lo : g_WaT_lo;
    g.Kb = Dn; g.Ktot = Dn;
    float* Out = blockIdx.z ? g_C : g_P;

    float d[4][4][4];
    ZERO_ACC(d)
    mma_gemm_body(smem, g, r0, n0, d, nullptr);

    int tid = threadIdx.x, lane = tid & 31, wid = tid >> 5;
    int wm = (wid & 1) * 64, wn = (wid >> 1) * 32;
#pragma unroll
    for (int f = 0; f < 4; f++) {
        int row = r0 + wm + f*16 + (lane >> 2);
#pragma unroll
        for (int nf = 0; nf < 4; nf++) {
            int col = n0 + wn + nf*8 + (lane & 3)*2;
            *(float2*)&Out[(long)row*Dn + col]     = make_float2(d[f][nf][0], d[f][nf][1]);
            *(float2*)&Out[(long)(row+8)*Dn + col] = make_float2(d[f][nf][2], d[f][nf][3]);
        }
    }
}

// ---------------------------------------------------------------------------
// 5) logits = [H | CTX] @ fc_W + fc_b  — mma.sync
__global__ void __launch_bounds__(256) k_logits_mma(
    const float* __restrict__ fcb, float* __restrict__ out)
{
    extern __shared__ char smem[];
    int r0 = blockIdx.x * 128;
    int n0 = blockIdx.y * 128;

    MMAArgs g;
    g.Ahi0 = g_Hb_hi; g.Alo0 = g_Hb_lo;
    g.Ahi1 = g_Xb_hi; g.Alo1 = g_Xb_lo;
    g.ksplit = Dn; g.Ka = Dn;
    g.Bhi = g_fcWT_hi; g.Blo = g_fcWT_lo;
    g.Kb = 2*Dn; g.Ktot = 2*Dn;

    float d[4][4][4];
    ZERO_ACC(d)
    mma_gemm_body(smem, g, r0, n0, d, nullptr);

    int tid = threadIdx.x, lane = tid & 31, wid = tid >> 5;
    int wm = (wid & 1) * 64, wn = (wid >> 1) * 32;
#pragma unroll
    for (int f = 0; f < 4; f++) {
        int r1 = r0 + wm + f*16 + (lane >> 2);
        int r2 = r1 + 8;
        int t1 = r1 >> 6, b1 = r1 & 63;
        int t2 = r2 >> 6, b2 = r2 & 63;
        float* o1 = &out[((long)b1*Tn + t1)*Vn];
        float* o2 = &out[((long)b2*Tn + t2)*Vn];
#pragma unroll
        for (int nf = 0; nf < 4; nf++) {
            int col = n0 + wn + nf*8 + (lane & 3)*2;
            float2 bv = *(const float2*)&fcb[col];
            *(float2*)&o1[col] = make_float2(d[f][nf][0] + bv.x, d[f][nf][1] + bv.y);
            *(float2*)&o2[col] = make_float2(d[f][nf][2] + bv.x, d[f][nf][3] + bv.y);
        }
    }
}

// ---------------------------------------------------------------------------
// 4) Bahdanau attention (MUFU floor); pass-3 writes split-bf16 ctx directly.
__global__ void __launch_bounds__(256) k_attn(const float* __restrict__ vat) {
    __shared__ float Cs[TT][Dn - 4];
    __shared__ float Cs2[TT][4];
    __shared__ float EsT[Tn][TT];
    int b  = blockIdx.y;
    int t0 = blockIdx.x * TT;
    int tid = threadIdx.x;
    int warp = tid >> 5, lane = tid & 31;

    for (int idx = tid; idx < TT*Dn; idx += 256) {
        int q = idx / Dn, d2 = idx % Dn;
        float v = g_C[((t0+q)*Bn + b)*Dn + d2];
        if (d2 < Dn - 4) Cs[q][d2] = v; else Cs2[q][d2 - (Dn-4)] = v;
    }
    float vreg[8];
#pragma unroll
    for (int j = 0; j < 8; j++) vreg[j] = vat[lane + 32*j];
    __syncthreads();

    int t_hi = t0 + TT;
    for (int tp = warp; tp < t_hi; tp += 8) {
        float p[8];
#pragma unroll
        for (int j = 0; j < 8; j++) p[j] = g_P[(tp*Bn + b)*Dn + lane + 32*j];
#pragma unroll
        for (int q = 0; q < TT; q++) {
            float s = 0.f;
#pragma unroll
            for (int j = 0; j < 8; j++) {
                int d2 = lane + 32*j;
                float cv = (d2 < Dn - 4) ? Cs[q][d2] : Cs2[q][d2 - (Dn-4)];
                float z = p[j] + cv;
                float th; asm("tanh.approx.f32 %0, %1;" : "=f"(th) : "f"(z));
                s = fmaf(vreg[j], th, s);
            }
#pragma unroll
            for (int o = 16; o; o >>= 1) s += __shfl_xor_sync(0xffffffffu, s, o);
            if (lane == 0) EsT[tp][q] = s;
        }
    }
    __syncthreads();

    for (int q = warp; q < TT; q += 8) {
        int tg = t0 + q;
        float mx = -3.4e38f;
        for (int tp = lane; tp < tg; tp += 32) mx = fmaxf(mx, EsT[tp][q]);
#pragma unroll
        for (int o = 16; o; o >>= 1) mx = fmaxf(mx, __shfl_xor_sync(0xffffffffu, mx, o));
        float sum = 0.f;
        for (int tp = lane; tp < tg; tp += 32) {
            float e = __expf(EsT[tp][q] - mx);
            EsT[tp][q] = e; sum += e;
        }
#pragma unroll
        for (int o = 16; o; o >>= 1) sum += __shfl_xor_sync(0xffffffffu, sum, o);
        float inv = tg > 0 ? 1.f / sum : 0.f;
        for (int tp = lane; tp < t_hi; tp += 32) {
            float wv = (tp < tg) ? EsT[tp][q] * inv : 0.f;
            EsT[tp][q] = wv;
        }
    }
    __syncthreads();

    int d = tid;
    float acc[TT];
#pragma unroll
    for (int q = 0; q < TT; q++) acc[q] = 0.f;
    int tmax = t0 + TT - 1;
    for (int tp = 0; tp < tmax; tp++) {
        float hval = g_H[(tp*Bn + b)*Dn + d];
#pragma unroll
        for (int q = 0; q < TT; q += 4) {
            float4 w = *(const float4*)&EsT[tp][q];
            acc[q]   = fmaf(w.x, hval, acc[q]);
            acc[q+1] = fmaf(w.y, hval, acc[q+1]);
            acc[q+2] = fmaf(w.z, hval, acc[q+2]);
            acc[q+3] = fmaf(w.w, hval, acc[q+3]);
        }
    }
#pragma unroll
    for (int q = 0; q < TT; q++) {
        int tg = t0 + q;
        float c = acc[q];
        if (tg == 0) c = g_H[b*Dn + d];
        int gi = (tg*Bn + b)*Dn + d;
        bf16 hh, hl; split_bf16(c, hh, hl);
        g_Xb_hi[gi] = hh; g_Xb_lo[gi] = hl;
    }
}

// ---------------------------------------------------------------------------
extern "C" void kernel_launch(void* const* d_in, const int* in_sizes, int n_in,
                              void* d_out, int out_size)
{
    const int*   x     = (const int*)  d_in[0];
    const float* embed = (const float*)d_in[1];
    const float* Wih   = (const float*)d_in[2];
    const float* Whh   = (const float*)d_in[3];
    const float* bh    = (const float*)d_in[4];
    const float* Wat   = (const float*)d_in[5];
    const float* Uat   = (const float*)d_in[6];
    const float* vat   = (const float*)d_in[7];
    const float* fcW   = (const float*)d_in[8];
    const float* fcb   = (const float*)d_in[9];
    float* out = (float*)d_out;

    int rnn_smem = 512*4 + 12*256*16;   // 51200
    cudaFuncSetAttribute(k_rnn,        cudaFuncAttributeMaxDynamicSharedMemorySize, rnn_smem);
    cudaFuncSetAttribute(k_embed_mma,  cudaFuncAttributeMaxDynamicSharedMemorySize, MMA_SMEM);
    cudaFuncSetAttribute(k_proj_mma,   cudaFuncAttributeMaxDynamicSharedMemorySize, MMA_SMEM);
    cudaFuncSetAttribute(k_logits_mma, cudaFuncAttributeMaxDynamicSharedMemorySize, MMA_SMEM);

    k_transpose<<<Dn, Dn>>>(Whh);
    k_cvt_all<<<491520/256, 256>>>(Wat, Uat, fcW, Wih, embed);
    k_embed_mma<<<dim3((Tn*Bn)/128, Dn/128), 256, MMA_SMEM>>>(x, bh);
    k_rnn<<<Bn, 256, rnn_smem>>>();
    k_proj_mma<<<dim3((Tn*Bn)/128, Dn/128, 2), 256, MMA_SMEM>>>();
    k_attn<<<dim3(Tn/TT, Bn), 256>>>(vat);
    k_logits_mma<<<dim3((Tn*Bn)/128, Vn/128), 256, MMA_SMEM>>>(fcb, out);
}